// round 8
// baseline (speedup 1.0000x reference)
#include <cuda_runtime.h>
#include <cstdint>

#define MAXN 100000
#define MAXE 1600000
#define FIN 128
#define FH 64
#define FO 16
#define SCAN_B 1024
#define MAXBLK 128
#define G1_ROWS 64
#define G1_THREADS 512
#define G1_SMEM ((FIN * FH + G1_ROWS * FIN) * 4)  // 32KB (Wt) + 32KB (x) = 64KB

// Scratch (device globals: allocation-free)
__device__ int    g_is64;
__device__ float  g_dinv[MAXN];
__device__ int    g_cnt[MAXN];
__device__ int    g_rowstart[MAXN];
__device__ int    g_cursor[MAXN];
__device__ int    g_blocksum[MAXBLK];
__device__ int    g_csrc[MAXE];
__device__ float  g_cnorm[MAXE];
__device__ float4 g_h1[(size_t)MAXN * (FH / 4)];
__device__ float4 g_z [(size_t)MAXN * (FH / 4)];
__device__ float4 g_h2[(size_t)MAXN * (FO / 4)];

__device__ __forceinline__ int edge_src(const void* ei, int E, int e) {
    return g_is64 ? (int)((const long long*)ei)[e] : ((const int*)ei)[e];
}
__device__ __forceinline__ int edge_dst(const void* ei, int E, int e) {
    return g_is64 ? (int)((const long long*)ei)[(size_t)E + e]
                  : ((const int*)ei)[(size_t)E + e];
}

// ---------------------------------------------------------------------------
__global__ void probe_kernel(const void* ei, int E, int n) {
    if (threadIdx.x != 0 || blockIdx.x != 0) return;
    const long long* p = (const long long*)ei;
    int ok64 = 1;
    int m = E < 64 ? E : 64;
    for (int i = 0; i < m; i++) {
        long long v = p[i];
        long long w = p[(size_t)E + i];
        if (v < 0 || v >= n || w < 0 || w >= n) { ok64 = 0; break; }
    }
    g_is64 = ok64;
}

__global__ void init_kernel(int n) {
    int i = blockIdx.x * blockDim.x + threadIdx.x;
    if (i < n) g_cnt[i] = 0;
}

__global__ void cnt_kernel(const void* __restrict__ ei, int E) {
    int e = blockIdx.x * blockDim.x + threadIdx.x;
    if (e >= E) return;
    atomicAdd(&g_cnt[edge_dst(ei, E, e)], 1);
}

// ---------------------------------------------------------------------------
// h1 = x @ W1 via packed fma.rn.f32x2 (FFMA2). W1 transposed + XOR-swizzled
// in smem so both FFMA2 operands are naturally 64-bit packed over k.
// sWt float4-unit index: col*32 + ((k>>2) ^ (col & 31))
// ---------------------------------------------------------------------------
__global__ void gemm1_kernel(const float* __restrict__ x,
                             const float* __restrict__ W1, int n) {
    extern __shared__ float smem[];
    float* sWt = smem;               // 64 cols x 128 k (swizzled f4 units), 32KB
    float* sx  = smem + FIN * FH;    // 64 rows x 128 k, linear, 32KB
    int t = threadIdx.x;

    // Load W1 [k][col] -> transposed swizzled sWt. Conflict-free scalar writes.
    #pragma unroll
    for (int i = t; i < FIN * FH; i += G1_THREADS) {
        int k = i >> 6, col = i & 63;
        int unit = col * 32 + ((k >> 2) ^ (col & 31));
        sWt[unit * 4 + (k & 3)] = W1[i];
    }

    int rowBase = blockIdx.x * G1_ROWS;
    #pragma unroll
    for (int i = t; i < G1_ROWS * FIN / 4; i += G1_THREADS) {
        int r = i / (FIN / 4), c = i % (FIN / 4);
        int row = rowBase + r;
        float4 val = (row < n) ? ((const float4*)(x + (size_t)row * FIN))[c]
                               : make_float4(0.f, 0.f, 0.f, 0.f);
        ((float4*)(sx + r * FIN))[c] = val;
    }
    __syncthreads();

    int col = t & 63;
    int rg = t >> 6;  // 0..7 -> rows rg*8 .. rg*8+7

    uint32_t wbase = (uint32_t)__cvta_generic_to_shared(sWt);
    uint32_t xbase = (uint32_t)__cvta_generic_to_shared(sx + (rg * 8) * FIN);

    uint64_t acc2[8];
    #pragma unroll
    for (int i = 0; i < 8; i++) acc2[i] = 0ull;

    #pragma unroll
    for (int k4 = 0; k4 < FIN / 4; k4++) {
        uint64_t w01, w23;
        uint32_t waddr = wbase + (uint32_t)((col * 32 + (k4 ^ (col & 31))) * 16);
        asm volatile("ld.shared.v2.b64 {%0, %1}, [%2];"
                     : "=l"(w01), "=l"(w23) : "r"(waddr));
        #pragma unroll
        for (int i = 0; i < 8; i++) {
            uint64_t x01, x23;
            uint32_t xaddr = xbase + (uint32_t)(i * FIN * 4 + k4 * 16);
            asm volatile("ld.shared.v2.b64 {%0, %1}, [%2];"
                         : "=l"(x01), "=l"(x23) : "r"(xaddr));
            asm volatile("fma.rn.f32x2 %0, %1, %2, %0;"
                         : "+l"(acc2[i]) : "l"(x01), "l"(w01));
            asm volatile("fma.rn.f32x2 %0, %1, %2, %0;"
                         : "+l"(acc2[i]) : "l"(x23), "l"(w23));
        }
    }

    float* h1 = (float*)g_h1;
    #pragma unroll
    for (int i = 0; i < 8; i++) {
        uint32_t lo32 = (uint32_t)(acc2[i] & 0xffffffffull);
        uint32_t hi32 = (uint32_t)(acc2[i] >> 32);
        float s = __uint_as_float(lo32) + __uint_as_float(hi32);
        int row = rowBase + rg * 8 + i;
        if (row < n) h1[(size_t)row * FH + col] = s;
    }
}

// ---------------------------------------------------------------------------
// hierarchical exclusive scan of g_cnt -> g_rowstart (+ cursor copy)
// ---------------------------------------------------------------------------
__global__ void scan1_kernel(int n) {
    __shared__ int s[SCAN_B];
    int t = threadIdx.x;
    int gid = blockIdx.x * SCAN_B + t;
    int v = (gid < n) ? g_cnt[gid] : 0;
    s[t] = v;
    __syncthreads();
    #pragma unroll
    for (int off = 1; off < SCAN_B; off <<= 1) {
        int u = (t >= off) ? s[t - off] : 0;
        __syncthreads();
        s[t] += u;
        __syncthreads();
    }
    if (gid < n) g_rowstart[gid] = s[t] - v;
    if (t == SCAN_B - 1) g_blocksum[blockIdx.x] = s[t];
}

__global__ void scan2_kernel(int nb) {
    __shared__ int s[MAXBLK];
    int t = threadIdx.x;
    int v = (t < nb) ? g_blocksum[t] : 0;
    s[t] = v;
    __syncthreads();
    #pragma unroll
    for (int off = 1; off < MAXBLK; off <<= 1) {
        int u = (t >= off) ? s[t - off] : 0;
        __syncthreads();
        s[t] += u;
        __syncthreads();
    }
    if (t < nb) g_blocksum[t] = s[t] - v;
}

__global__ void scan3_kernel(int n) {
    int gid = blockIdx.x * blockDim.x + threadIdx.x;
    if (gid >= n) return;
    int r = g_rowstart[gid] + g_blocksum[gid >> 10];
    g_rowstart[gid] = r;
    g_cursor[gid] = r;
}

__global__ void build_kernel(const void* __restrict__ ei,
                             const float* __restrict__ ew, int E) {
    int e = blockIdx.x * blockDim.x + threadIdx.x;
    if (e >= E) return;
    int s = edge_src(ei, E, e);
    int d = edge_dst(ei, E, e);
    int pos = atomicAdd(&g_cursor[d], 1);
    g_csrc[pos] = s;
    g_cnorm[pos] = ew[e];
}

__global__ void dinv_kernel(int n) {
    int warp = (blockIdx.x * blockDim.x + threadIdx.x) >> 5;
    if (warp >= n) return;
    int lane = threadIdx.x & 31;
    int start = g_rowstart[warp];
    int end = start + g_cnt[warp];
    float s = 0.f;
    for (int j = start + lane; j < end; j += 32) s += g_cnorm[j];
    #pragma unroll
    for (int off = 16; off > 0; off >>= 1)
        s += __shfl_xor_sync(0xffffffffu, s, off);
    if (lane == 0) g_dinv[warp] = rsqrtf(1.0f + s);
}

__global__ void norm_kernel(int n) {
    int warp = (blockIdx.x * blockDim.x + threadIdx.x) >> 5;
    if (warp >= n) return;
    int lane = threadIdx.x & 31;
    float dd = g_dinv[warp];
    int start = g_rowstart[warp];
    int end = start + g_cnt[warp];
    for (int j = start + lane; j < end; j += 32)
        g_cnorm[j] = g_dinv[g_csrc[j]] * g_cnorm[j] * dd;
}

// ---------------------------------------------------------------------------
// agg1: one warp per dst node, lanes own float2 of 64 features, 8-deep unroll
// ---------------------------------------------------------------------------
__global__ void agg1_kernel(const float* __restrict__ b1, int n) {
    int warp = (blockIdx.x * blockDim.x + threadIdx.x) >> 5;
    if (warp >= n) return;
    int lane = threadIdx.x & 31;
    const float2* h1 = (const float2*)g_h1;
    int start = g_rowstart[warp];
    int end = start + g_cnt[warp];
    float2 acc = make_float2(0.f, 0.f);

    int j = start;
    for (; j + 8 <= end; j += 8) {
        int   s0 = g_csrc[j],  s1 = g_csrc[j+1],  s2 = g_csrc[j+2],  s3 = g_csrc[j+3];
        int   s4 = g_csrc[j+4], s5 = g_csrc[j+5], s6 = g_csrc[j+6], s7 = g_csrc[j+7];
        float n0 = g_cnorm[j],   n1 = g_cnorm[j+1], n2 = g_cnorm[j+2], n3 = g_cnorm[j+3];
        float n4 = g_cnorm[j+4], n5 = g_cnorm[j+5], n6 = g_cnorm[j+6], n7 = g_cnorm[j+7];
        float2 v0 = h1[(size_t)s0 * 32 + lane];
        float2 v1 = h1[(size_t)s1 * 32 + lane];
        float2 v2 = h1[(size_t)s2 * 32 + lane];
        float2 v3 = h1[(size_t)s3 * 32 + lane];
        float2 v4 = h1[(size_t)s4 * 32 + lane];
        float2 v5 = h1[(size_t)s5 * 32 + lane];
        float2 v6 = h1[(size_t)s6 * 32 + lane];
        float2 v7 = h1[(size_t)s7 * 32 + lane];
        acc.x += n0 * v0.x + n1 * v1.x + n2 * v2.x + n3 * v3.x
               + n4 * v4.x + n5 * v5.x + n6 * v6.x + n7 * v7.x;
        acc.y += n0 * v0.y + n1 * v1.y + n2 * v2.y + n3 * v3.y
               + n4 * v4.y + n5 * v5.y + n6 * v6.y + n7 * v7.y;
    }
    for (; j < end; j++) {
        int s = g_csrc[j];
        float nm = g_cnorm[j];
        float2 v = h1[(size_t)s * 32 + lane];
        acc.x += nm * v.x;
        acc.y += nm * v.y;
    }
    float dv = g_dinv[warp];
    float self = dv * dv;
    float2 hs = h1[(size_t)warp * 32 + lane];
    acc.x += self * hs.x;
    acc.y += self * hs.y;
    acc.x = fmaxf(acc.x + b1[lane * 2 + 0], 0.f);
    acc.y = fmaxf(acc.y + b1[lane * 2 + 1], 0.f);
    ((float2*)g_z)[(size_t)warp * 32 + lane] = acc;
}

// ---------------------------------------------------------------------------
__global__ void gemm2_kernel(const float* __restrict__ W2, int n) {
    __shared__ float sW[FH * FO];
    for (int i = threadIdx.x; i < FH * FO; i += blockDim.x) sW[i] = W2[i];
    __syncthreads();

    int nn = blockIdx.x * blockDim.x + threadIdx.x;
    if (nn >= n) return;
    const float4* z4 = &g_z[(size_t)nn * (FH / 4)];
    float acc[FO];
    #pragma unroll
    for (int j = 0; j < FO; j++) acc[j] = 0.f;
    #pragma unroll
    for (int k4 = 0; k4 < FH / 4; k4++) {
        float4 zv = z4[k4];
        #pragma unroll
        for (int j = 0; j < FO; j++) {
            acc[j] += zv.x * sW[(k4 * 4 + 0) * FO + j];
            acc[j] += zv.y * sW[(k4 * 4 + 1) * FO + j];
            acc[j] += zv.z * sW[(k4 * 4 + 2) * FO + j];
            acc[j] += zv.w * sW[(k4 * 4 + 3) * FO + j];
        }
    }
    float4* o4 = &g_h2[(size_t)nn * (FO / 4)];
    o4[0] = make_float4(acc[0], acc[1], acc[2], acc[3]);
    o4[1] = make_float4(acc[4], acc[5], acc[6], acc[7]);
    o4[2] = make_float4(acc[8], acc[9], acc[10], acc[11]);
    o4[3] = make_float4(acc[12], acc[13], acc[14], acc[15]);
}

// ---------------------------------------------------------------------------
__global__ void agg2_kernel(const float* __restrict__ b2,
                            float* __restrict__ out, int n) {
    int gid = blockIdx.x * blockDim.x + threadIdx.x;
    int node = gid >> 4;
    bool live = node < n;
    if (!live) node = 0;
    int f = gid & 15;
    const float* h2 = (const float*)g_h2;
    int start = g_rowstart[node];
    int end = start + g_cnt[node];
    float acc = 0.f;

    int j = start;
    for (; j + 4 <= end; j += 4) {
        int   s0 = g_csrc[j],  s1 = g_csrc[j+1],  s2 = g_csrc[j+2],  s3 = g_csrc[j+3];
        float n0 = g_cnorm[j], n1 = g_cnorm[j+1], n2 = g_cnorm[j+2], n3 = g_cnorm[j+3];
        acc += n0 * h2[(size_t)s0 * FO + f] + n1 * h2[(size_t)s1 * FO + f]
             + n2 * h2[(size_t)s2 * FO + f] + n3 * h2[(size_t)s3 * FO + f];
    }
    for (; j < end; j++) {
        acc += g_cnorm[j] * h2[(size_t)g_csrc[j] * FO + f];
    }
    float dv = g_dinv[node];
    acc += dv * dv * h2[(size_t)node * FO + f] + b2[f];

    float m = acc;
    #pragma unroll
    for (int off = 8; off > 0; off >>= 1)
        m = fmaxf(m, __shfl_xor_sync(0xffffffffu, m, off));
    float e = expf(acc - m);
    float ssum = e;
    #pragma unroll
    for (int off = 8; off > 0; off >>= 1)
        ssum += __shfl_xor_sync(0xffffffffu, ssum, off);
    if (live) out[(size_t)node * FO + f] = acc - m - logf(ssum);
}

// ---------------------------------------------------------------------------
extern "C" void kernel_launch(void* const* d_in, const int* in_sizes, int n_in,
                              void* d_out, int out_size) {
    const float* x  = (const float*)d_in[0];
    const void*  ei = d_in[1];
    const float* ew = (const float*)d_in[2];
    const float* W1 = (const float*)d_in[3];
    const float* b1 = (const float*)d_in[4];
    const float* W2 = (const float*)d_in[5];
    const float* b2 = (const float*)d_in[6];
    float*       out = (float*)d_out;

    int n = in_sizes[0] / FIN;
    int E = in_sizes[2];

    cudaFuncSetAttribute(gemm1_kernel,
                         cudaFuncAttributeMaxDynamicSharedMemorySize, G1_SMEM);

    probe_kernel<<<1, 1>>>(ei, E, n);
    init_kernel<<<(n + 255) / 256, 256>>>(n);
    cnt_kernel<<<(E + 255) / 256, 256>>>(ei, E);

    // 4th launch -> profiled by ncu
    gemm1_kernel<<<(n + G1_ROWS - 1) / G1_ROWS, G1_THREADS, G1_SMEM>>>(x, W1, n);

    int nb = (n + SCAN_B - 1) / SCAN_B;
    scan1_kernel<<<nb, SCAN_B>>>(n);
    scan2_kernel<<<1, MAXBLK>>>(nb);
    scan3_kernel<<<(n + 255) / 256, 256>>>(n);

    build_kernel<<<(E + 255) / 256, 256>>>(ei, ew, E);

    long long tw = (long long)n * 32;
    dinv_kernel<<<(int)((tw + 255) / 256), 256>>>(n);
    norm_kernel<<<(int)((tw + 255) / 256), 256>>>(n);

    agg1_kernel<<<(int)((tw + 255) / 256), 256>>>(b1, n);

    gemm2_kernel<<<(n + 255) / 256, 256>>>(W2, n);

    long long t2 = (long long)n * 16;
    agg2_kernel<<<(int)((t2 + 255) / 256), 256>>>(b2, out, n);
}

// round 9
// speedup vs baseline: 1.0469x; 1.0469x over previous
#include <cuda_runtime.h>
#include <cstdint>

#define MAXN 100000
#define MAXE 1600000
#define FIN 128
#define FH 64
#define FO 16
#define SCAN_B 1024
#define MAXBLK 128
#define G1_ROWS 128
#define G1_THREADS 512
#define G1_SMEM ((FIN * FH + G1_ROWS * FIN) * 4)  // 32KB (Wt) + 64KB (x) = 96KB

// Scratch (device globals: allocation-free)
__device__ int    g_is64;
__device__ float  g_dinv[MAXN];
__device__ int    g_cnt[MAXN];
__device__ int    g_rowstart[MAXN];
__device__ int    g_cursor[MAXN];
__device__ int    g_blocksum[MAXBLK];
__device__ int    g_csrc[MAXE];
__device__ float  g_cnorm[MAXE];
__device__ float4 g_h1[(size_t)MAXN * (FH / 4)];
__device__ float4 g_z [(size_t)MAXN * (FH / 4)];
__device__ float4 g_h2[(size_t)MAXN * (FO / 4)];

__device__ __forceinline__ int edge_src(const void* ei, int E, int e) {
    return g_is64 ? (int)((const long long*)ei)[e] : ((const int*)ei)[e];
}
__device__ __forceinline__ int edge_dst(const void* ei, int E, int e) {
    return g_is64 ? (int)((const long long*)ei)[(size_t)E + e]
                  : ((const int*)ei)[(size_t)E + e];
}

// ---------------------------------------------------------------------------
__global__ void probe_kernel(const void* ei, int E, int n) {
    if (threadIdx.x != 0 || blockIdx.x != 0) return;
    const long long* p = (const long long*)ei;
    int ok64 = 1;
    int m = E < 64 ? E : 64;
    for (int i = 0; i < m; i++) {
        long long v = p[i];
        long long w = p[(size_t)E + i];
        if (v < 0 || v >= n || w < 0 || w >= n) { ok64 = 0; break; }
    }
    g_is64 = ok64;
}

__global__ void init_kernel(int n) {
    int i = blockIdx.x * blockDim.x + threadIdx.x;
    if (i < n) g_cnt[i] = 0;
}

__global__ void cnt_kernel(const void* __restrict__ ei, int E) {
    int e = blockIdx.x * blockDim.x + threadIdx.x;
    if (e >= E) return;
    atomicAdd(&g_cnt[edge_dst(ei, E, e)], 1);
}

// ---------------------------------------------------------------------------
// h1 = x @ W1, FFMA2 + 2-column thread tile.
// Block tile: 128 rows x 64 cols, 512 threads.
// Thread: rows rg*8..rg*8+7 (rg = t>>5), cols {cp, cp+32} (cp = t&31).
// Wt swizzled: unit(col,k4) = col*32 + (k4 ^ (col&31)); conflict-free for
// both col=cp and col=cp+32 reads (same &31 class).
// LDS per k4: 8x16B x + 2x16B w = 160B for 128 scalar FMAs (1.25 B/FMA).
// ---------------------------------------------------------------------------
__global__ void gemm1_kernel(const float* __restrict__ x,
                             const float* __restrict__ W1, int n) {
    extern __shared__ float smem[];
    float* sWt = smem;               // 64 cols x 128 k (swizzled f4 units)
    float* sx  = smem + FIN * FH;    // 128 rows x 128 k, linear
    int t = threadIdx.x;

    // W1 [k][col] -> transposed swizzled sWt
    #pragma unroll
    for (int i = t; i < FIN * FH; i += G1_THREADS) {
        int k = i >> 6, col = i & 63;
        int unit = col * 32 + ((k >> 2) ^ (col & 31));
        sWt[unit * 4 + (k & 3)] = W1[i];
    }

    int rowBase = blockIdx.x * G1_ROWS;
    #pragma unroll
    for (int i = t; i < G1_ROWS * FIN / 4; i += G1_THREADS) {
        int r = i / (FIN / 4), c = i % (FIN / 4);
        int row = rowBase + r;
        float4 val = (row < n) ? ((const float4*)(x + (size_t)row * FIN))[c]
                               : make_float4(0.f, 0.f, 0.f, 0.f);
        ((float4*)(sx + r * FIN))[c] = val;
    }
    __syncthreads();

    int cp = t & 31;          // cols cp and cp+32
    int rg = t >> 5;          // 0..15 -> rows rg*8 .. rg*8+7

    uint32_t wbase = (uint32_t)__cvta_generic_to_shared(sWt);
    uint32_t xbase = (uint32_t)__cvta_generic_to_shared(sx + (rg * 8) * FIN);

    uint64_t accA[8], accB[8];
    #pragma unroll
    for (int i = 0; i < 8; i++) { accA[i] = 0ull; accB[i] = 0ull; }

    #pragma unroll
    for (int k4 = 0; k4 < FIN / 4; k4++) {
        int sw = k4 ^ cp;
        uint64_t wA01, wA23, wB01, wB23;
        uint32_t waddrA = wbase + (uint32_t)((cp * 32 + sw) * 16);
        uint32_t waddrB = waddrA + (uint32_t)(32 * 32 * 16);  // col+32 block
        asm volatile("ld.shared.v2.b64 {%0, %1}, [%2];"
                     : "=l"(wA01), "=l"(wA23) : "r"(waddrA));
        asm volatile("ld.shared.v2.b64 {%0, %1}, [%2];"
                     : "=l"(wB01), "=l"(wB23) : "r"(waddrB));
        #pragma unroll
        for (int i = 0; i < 8; i++) {
            uint64_t x01, x23;
            uint32_t xaddr = xbase + (uint32_t)(i * FIN * 4 + k4 * 16);
            asm volatile("ld.shared.v2.b64 {%0, %1}, [%2];"
                         : "=l"(x01), "=l"(x23) : "r"(xaddr));
            asm volatile("fma.rn.f32x2 %0, %1, %2, %0;"
                         : "+l"(accA[i]) : "l"(x01), "l"(wA01));
            asm volatile("fma.rn.f32x2 %0, %1, %2, %0;"
                         : "+l"(accA[i]) : "l"(x23), "l"(wA23));
            asm volatile("fma.rn.f32x2 %0, %1, %2, %0;"
                         : "+l"(accB[i]) : "l"(x01), "l"(wB01));
            asm volatile("fma.rn.f32x2 %0, %1, %2, %0;"
                         : "+l"(accB[i]) : "l"(x23), "l"(wB23));
        }
    }

    float* h1 = (float*)g_h1;
    #pragma unroll
    for (int i = 0; i < 8; i++) {
        int row = rowBase + rg * 8 + i;
        if (row < n) {
            float a = __uint_as_float((uint32_t)(accA[i] & 0xffffffffull))
                    + __uint_as_float((uint32_t)(accA[i] >> 32));
            float b = __uint_as_float((uint32_t)(accB[i] & 0xffffffffull))
                    + __uint_as_float((uint32_t)(accB[i] >> 32));
            h1[(size_t)row * FH + cp]      = a;
            h1[(size_t)row * FH + cp + 32] = b;
        }
    }
}

// ---------------------------------------------------------------------------
// hierarchical exclusive scan of g_cnt -> g_rowstart (+ cursor copy)
// ---------------------------------------------------------------------------
__global__ void scan1_kernel(int n) {
    __shared__ int s[SCAN_B];
    int t = threadIdx.x;
    int gid = blockIdx.x * SCAN_B + t;
    int v = (gid < n) ? g_cnt[gid] : 0;
    s[t] = v;
    __syncthreads();
    #pragma unroll
    for (int off = 1; off < SCAN_B; off <<= 1) {
        int u = (t >= off) ? s[t - off] : 0;
        __syncthreads();
        s[t] += u;
        __syncthreads();
    }
    if (gid < n) g_rowstart[gid] = s[t] - v;
    if (t == SCAN_B - 1) g_blocksum[blockIdx.x] = s[t];
}

__global__ void scan2_kernel(int nb) {
    __shared__ int s[MAXBLK];
    int t = threadIdx.x;
    int v = (t < nb) ? g_blocksum[t] : 0;
    s[t] = v;
    __syncthreads();
    #pragma unroll
    for (int off = 1; off < MAXBLK; off <<= 1) {
        int u = (t >= off) ? s[t - off] : 0;
        __syncthreads();
        s[t] += u;
        __syncthreads();
    }
    if (t < nb) g_blocksum[t] = s[t] - v;
}

__global__ void scan3_kernel(int n) {
    int gid = blockIdx.x * blockDim.x + threadIdx.x;
    if (gid >= n) return;
    int r = g_rowstart[gid] + g_blocksum[gid >> 10];
    g_rowstart[gid] = r;
    g_cursor[gid] = r;
}

__global__ void build_kernel(const void* __restrict__ ei,
                             const float* __restrict__ ew, int E) {
    int e = blockIdx.x * blockDim.x + threadIdx.x;
    if (e >= E) return;
    int s = edge_src(ei, E, e);
    int d = edge_dst(ei, E, e);
    int pos = atomicAdd(&g_cursor[d], 1);
    g_csrc[pos] = s;
    g_cnorm[pos] = ew[e];
}

__global__ void dinv_kernel(int n) {
    int warp = (blockIdx.x * blockDim.x + threadIdx.x) >> 5;
    if (warp >= n) return;
    int lane = threadIdx.x & 31;
    int start = g_rowstart[warp];
    int end = start + g_cnt[warp];
    float s = 0.f;
    for (int j = start + lane; j < end; j += 32) s += g_cnorm[j];
    #pragma unroll
    for (int off = 16; off > 0; off >>= 1)
        s += __shfl_xor_sync(0xffffffffu, s, off);
    if (lane == 0) g_dinv[warp] = rsqrtf(1.0f + s);
}

__global__ void norm_kernel(int n) {
    int warp = (blockIdx.x * blockDim.x + threadIdx.x) >> 5;
    if (warp >= n) return;
    int lane = threadIdx.x & 31;
    float dd = g_dinv[warp];
    int start = g_rowstart[warp];
    int end = start + g_cnt[warp];
    for (int j = start + lane; j < end; j += 32)
        g_cnorm[j] = g_dinv[g_csrc[j]] * g_cnorm[j] * dd;
}

// ---------------------------------------------------------------------------
// agg1: one warp per dst node, lanes own float2 of 64 features, 8-deep unroll
// ---------------------------------------------------------------------------
__global__ void agg1_kernel(const float* __restrict__ b1, int n) {
    int warp = (blockIdx.x * blockDim.x + threadIdx.x) >> 5;
    if (warp >= n) return;
    int lane = threadIdx.x & 31;
    const float2* h1 = (const float2*)g_h1;
    int start = g_rowstart[warp];
    int end = start + g_cnt[warp];
    float2 acc = make_float2(0.f, 0.f);

    int j = start;
    for (; j + 8 <= end; j += 8) {
        int   s0 = g_csrc[j],  s1 = g_csrc[j+1],  s2 = g_csrc[j+2],  s3 = g_csrc[j+3];
        int   s4 = g_csrc[j+4], s5 = g_csrc[j+5], s6 = g_csrc[j+6], s7 = g_csrc[j+7];
        float n0 = g_cnorm[j],   n1 = g_cnorm[j+1], n2 = g_cnorm[j+2], n3 = g_cnorm[j+3];
        float n4 = g_cnorm[j+4], n5 = g_cnorm[j+5], n6 = g_cnorm[j+6], n7 = g_cnorm[j+7];
        float2 v0 = h1[(size_t)s0 * 32 + lane];
        float2 v1 = h1[(size_t)s1 * 32 + lane];
        float2 v2 = h1[(size_t)s2 * 32 + lane];
        float2 v3 = h1[(size_t)s3 * 32 + lane];
        float2 v4 = h1[(size_t)s4 * 32 + lane];
        float2 v5 = h1[(size_t)s5 * 32 + lane];
        float2 v6 = h1[(size_t)s6 * 32 + lane];
        float2 v7 = h1[(size_t)s7 * 32 + lane];
        acc.x += n0 * v0.x + n1 * v1.x + n2 * v2.x + n3 * v3.x
               + n4 * v4.x + n5 * v5.x + n6 * v6.x + n7 * v7.x;
        acc.y += n0 * v0.y + n1 * v1.y + n2 * v2.y + n3 * v3.y
               + n4 * v4.y + n5 * v5.y + n6 * v6.y + n7 * v7.y;
    }
    for (; j < end; j++) {
        int s = g_csrc[j];
        float nm = g_cnorm[j];
        float2 v = h1[(size_t)s * 32 + lane];
        acc.x += nm * v.x;
        acc.y += nm * v.y;
    }
    float dv = g_dinv[warp];
    float self = dv * dv;
    float2 hs = h1[(size_t)warp * 32 + lane];
    acc.x += self * hs.x;
    acc.y += self * hs.y;
    acc.x = fmaxf(acc.x + b1[lane * 2 + 0], 0.f);
    acc.y = fmaxf(acc.y + b1[lane * 2 + 1], 0.f);
    ((float2*)g_z)[(size_t)warp * 32 + lane] = acc;
}

// ---------------------------------------------------------------------------
__global__ void gemm2_kernel(const float* __restrict__ W2, int n) {
    __shared__ float sW[FH * FO];
    for (int i = threadIdx.x; i < FH * FO; i += blockDim.x) sW[i] = W2[i];
    __syncthreads();

    int nn = blockIdx.x * blockDim.x + threadIdx.x;
    if (nn >= n) return;
    const float4* z4 = &g_z[(size_t)nn * (FH / 4)];
    float acc[FO];
    #pragma unroll
    for (int j = 0; j < FO; j++) acc[j] = 0.f;
    #pragma unroll
    for (int k4 = 0; k4 < FH / 4; k4++) {
        float4 zv = z4[k4];
        #pragma unroll
        for (int j = 0; j < FO; j++) {
            acc[j] += zv.x * sW[(k4 * 4 + 0) * FO + j];
            acc[j] += zv.y * sW[(k4 * 4 + 1) * FO + j];
            acc[j] += zv.z * sW[(k4 * 4 + 2) * FO + j];
            acc[j] += zv.w * sW[(k4 * 4 + 3) * FO + j];
        }
    }
    float4* o4 = &g_h2[(size_t)nn * (FO / 4)];
    o4[0] = make_float4(acc[0], acc[1], acc[2], acc[3]);
    o4[1] = make_float4(acc[4], acc[5], acc[6], acc[7]);
    o4[2] = make_float4(acc[8], acc[9], acc[10], acc[11]);
    o4[3] = make_float4(acc[12], acc[13], acc[14], acc[15]);
}

// ---------------------------------------------------------------------------
__global__ void agg2_kernel(const float* __restrict__ b2,
                            float* __restrict__ out, int n) {
    int gid = blockIdx.x * blockDim.x + threadIdx.x;
    int node = gid >> 4;
    bool live = node < n;
    if (!live) node = 0;
    int f = gid & 15;
    const float* h2 = (const float*)g_h2;
    int start = g_rowstart[node];
    int end = start + g_cnt[node];
    float acc = 0.f;

    int j = start;
    for (; j + 4 <= end; j += 4) {
        int   s0 = g_csrc[j],  s1 = g_csrc[j+1],  s2 = g_csrc[j+2],  s3 = g_csrc[j+3];
        float n0 = g_cnorm[j], n1 = g_cnorm[j+1], n2 = g_cnorm[j+2], n3 = g_cnorm[j+3];
        acc += n0 * h2[(size_t)s0 * FO + f] + n1 * h2[(size_t)s1 * FO + f]
             + n2 * h2[(size_t)s2 * FO + f] + n3 * h2[(size_t)s3 * FO + f];
    }
    for (; j < end; j++) {
        acc += g_cnorm[j] * h2[(size_t)g_csrc[j] * FO + f];
    }
    float dv = g_dinv[node];
    acc += dv * dv * h2[(size_t)node * FO + f] + b2[f];

    float m = acc;
    #pragma unroll
    for (int off = 8; off > 0; off >>= 1)
        m = fmaxf(m, __shfl_xor_sync(0xffffffffu, m, off));
    float e = expf(acc - m);
    float ssum = e;
    #pragma unroll
    for (int off = 8; off > 0; off >>= 1)
        ssum += __shfl_xor_sync(0xffffffffu, ssum, off);
    if (live) out[(size_t)node * FO + f] = acc - m - logf(ssum);
}

// ---------------------------------------------------------------------------
extern "C" void kernel_launch(void* const* d_in, const int* in_sizes, int n_in,
                              void* d_out, int out_size) {
    const float* x  = (const float*)d_in[0];
    const void*  ei = d_in[1];
    const float* ew = (const float*)d_in[2];
    const float* W1 = (const float*)d_in[3];
    const float* b1 = (const float*)d_in[4];
    const float* W2 = (const float*)d_in[5];
    const float* b2 = (const float*)d_in[6];
    float*       out = (float*)d_out;

    int n = in_sizes[0] / FIN;
    int E = in_sizes[2];

    cudaFuncSetAttribute(gemm1_kernel,
                         cudaFuncAttributeMaxDynamicSharedMemorySize, G1_SMEM);

    probe_kernel<<<1, 1>>>(ei, E, n);
    init_kernel<<<(n + 255) / 256, 256>>>(n);
    cnt_kernel<<<(E + 255) / 256, 256>>>(ei, E);

    // 4th launch -> profiled by ncu
    gemm1_kernel<<<(n + G1_ROWS - 1) / G1_ROWS, G1_THREADS, G1_SMEM>>>(x, W1, n);

    int nb = (n + SCAN_B - 1) / SCAN_B;
    scan1_kernel<<<nb, SCAN_B>>>(n);
    scan2_kernel<<<1, MAXBLK>>>(nb);
    scan3_kernel<<<(n + 255) / 256, 256>>>(n);

    build_kernel<<<(E + 255) / 256, 256>>>(ei, ew, E);

    long long tw = (long long)n * 32;
    dinv_kernel<<<(int)((tw + 255) / 256), 256>>>(n);
    norm_kernel<<<(int)((tw + 255) / 256), 256>>>(n);

    agg1_kernel<<<(int)((tw + 255) / 256), 256>>>(b1, n);

    gemm2_kernel<<<(n + 255) / 256, 256>>>(W2, n);

    long long t2 = (long long)n * 16;
    agg2_kernel<<<(int)((t2 + 255) / 256), 256>>>(b2, out, n);
}

// round 10
// speedup vs baseline: 1.1608x; 1.1088x over previous
#include <cuda_runtime.h>
#include <cstdint>

#define MAXN 100000
#define MAXE 1600000
#define FIN 128
#define FH 64
#define FO 16
#define SCAN_B 1024
#define MAXBLK 128
#define G1_ROWS 128
#define G1_THREADS 512
#define G1_SMEM ((FIN * FH + G1_ROWS * FIN) * 4)  // 32KB (Wt) + 64KB (x) = 96KB

// Scratch (device globals: allocation-free)
__device__ int    g_is64;
__device__ float  g_deg[MAXN];
__device__ float  g_dinv[MAXN];
__device__ int    g_cnt[MAXN];
__device__ int    g_rowstart[MAXN];
__device__ int    g_cursor[MAXN];
__device__ int    g_blocksum[MAXBLK];
__device__ int    g_csrc[MAXE];
__device__ float  g_cnorm[MAXE];
__device__ float4 g_h1[(size_t)MAXN * (FH / 4)];
__device__ float4 g_z [(size_t)MAXN * (FH / 4)];
__device__ float4 g_h2[(size_t)MAXN * (FO / 4)];

__device__ __forceinline__ int edge_src(const void* ei, int E, int e) {
    return g_is64 ? (int)((const long long*)ei)[e] : ((const int*)ei)[e];
}
__device__ __forceinline__ int edge_dst(const void* ei, int E, int e) {
    return g_is64 ? (int)((const long long*)ei)[(size_t)E + e]
                  : ((const int*)ei)[(size_t)E + e];
}

// ---------------------------------------------------------------------------
__global__ void probe_kernel(const void* ei, int E, int n) {
    if (threadIdx.x != 0 || blockIdx.x != 0) return;
    const long long* p = (const long long*)ei;
    int ok64 = 1;
    int m = E < 64 ? E : 64;
    for (int i = 0; i < m; i++) {
        long long v = p[i];
        long long w = p[(size_t)E + i];
        if (v < 0 || v >= n || w < 0 || w >= n) { ok64 = 0; break; }
    }
    g_is64 = ok64;
}

__global__ void init_kernel(int n) {
    int i = blockIdx.x * blockDim.x + threadIdx.x;
    if (i < n) { g_cnt[i] = 0; g_deg[i] = 1.0f; }   // self-loop weight 1
}

// fused: edge count (int atomic) + weighted in-degree (float atomic)
__global__ void cnt_kernel(const void* __restrict__ ei,
                           const float* __restrict__ ew, int E) {
    int e = blockIdx.x * blockDim.x + threadIdx.x;
    if (e >= E) return;
    int d = edge_dst(ei, E, e);
    atomicAdd(&g_cnt[d], 1);
    atomicAdd(&g_deg[d], ew[e]);
}

// ---------------------------------------------------------------------------
// h1 = x @ W1, FFMA2 + 2-column thread tile, 2 blocks/SM via launch bounds.
// Block tile: 128 rows x 64 cols, 512 threads.
// ---------------------------------------------------------------------------
__global__ void __launch_bounds__(G1_THREADS, 2)
gemm1_kernel(const float* __restrict__ x,
             const float* __restrict__ W1, int n) {
    extern __shared__ float smem[];
    float* sWt = smem;               // 64 cols x 128 k (swizzled f4 units)
    float* sx  = smem + FIN * FH;    // 128 rows x 128 k, linear
    int t = threadIdx.x;

    // W1 [k][col] -> transposed swizzled sWt
    #pragma unroll
    for (int i = t; i < FIN * FH; i += G1_THREADS) {
        int k = i >> 6, col = i & 63;
        int unit = col * 32 + ((k >> 2) ^ (col & 31));
        sWt[unit * 4 + (k & 3)] = W1[i];
    }

    int rowBase = blockIdx.x * G1_ROWS;
    #pragma unroll
    for (int i = t; i < G1_ROWS * FIN / 4; i += G1_THREADS) {
        int r = i / (FIN / 4), c = i % (FIN / 4);
        int row = rowBase + r;
        float4 val = (row < n) ? ((const float4*)(x + (size_t)row * FIN))[c]
                               : make_float4(0.f, 0.f, 0.f, 0.f);
        ((float4*)(sx + r * FIN))[c] = val;
    }
    __syncthreads();

    int cp = t & 31;          // cols cp and cp+32
    int rg = t >> 5;          // 0..15 -> rows rg*8 .. rg*8+7

    uint32_t wbase = (uint32_t)__cvta_generic_to_shared(sWt);
    uint32_t xbase = (uint32_t)__cvta_generic_to_shared(sx + (rg * 8) * FIN);

    uint64_t accA[8], accB[8];
    #pragma unroll
    for (int i = 0; i < 8; i++) { accA[i] = 0ull; accB[i] = 0ull; }

    #pragma unroll
    for (int k4 = 0; k4 < FIN / 4; k4++) {
        int sw = k4 ^ cp;
        uint64_t wA01, wA23, wB01, wB23;
        uint32_t waddrA = wbase + (uint32_t)((cp * 32 + sw) * 16);
        uint32_t waddrB = waddrA + (uint32_t)(32 * 32 * 16);  // col+32 block
        asm volatile("ld.shared.v2.b64 {%0, %1}, [%2];"
                     : "=l"(wA01), "=l"(wA23) : "r"(waddrA));
        asm volatile("ld.shared.v2.b64 {%0, %1}, [%2];"
                     : "=l"(wB01), "=l"(wB23) : "r"(waddrB));
        #pragma unroll
        for (int i = 0; i < 8; i++) {
            uint64_t x01, x23;
            uint32_t xaddr = xbase + (uint32_t)(i * FIN * 4 + k4 * 16);
            asm volatile("ld.shared.v2.b64 {%0, %1}, [%2];"
                         : "=l"(x01), "=l"(x23) : "r"(xaddr));
            asm volatile("fma.rn.f32x2 %0, %1, %2, %0;"
                         : "+l"(accA[i]) : "l"(x01), "l"(wA01));
            asm volatile("fma.rn.f32x2 %0, %1, %2, %0;"
                         : "+l"(accA[i]) : "l"(x23), "l"(wA23));
            asm volatile("fma.rn.f32x2 %0, %1, %2, %0;"
                         : "+l"(accB[i]) : "l"(x01), "l"(wB01));
            asm volatile("fma.rn.f32x2 %0, %1, %2, %0;"
                         : "+l"(accB[i]) : "l"(x23), "l"(wB23));
        }
    }

    float* h1 = (float*)g_h1;
    #pragma unroll
    for (int i = 0; i < 8; i++) {
        int row = rowBase + rg * 8 + i;
        if (row < n) {
            float a = __uint_as_float((uint32_t)(accA[i] & 0xffffffffull))
                    + __uint_as_float((uint32_t)(accA[i] >> 32));
            float b = __uint_as_float((uint32_t)(accB[i] & 0xffffffffull))
                    + __uint_as_float((uint32_t)(accB[i] >> 32));
            h1[(size_t)row * FH + cp]      = a;
            h1[(size_t)row * FH + cp + 32] = b;
        }
    }
}

// ---------------------------------------------------------------------------
__global__ void dinv_kernel(int n) {
    int i = blockIdx.x * blockDim.x + threadIdx.x;
    if (i < n) g_dinv[i] = rsqrtf(g_deg[i]);   // deg >= 1
}

// hierarchical exclusive scan of g_cnt -> g_rowstart (+ cursor copy)
__global__ void scan1_kernel(int n) {
    __shared__ int s[SCAN_B];
    int t = threadIdx.x;
    int gid = blockIdx.x * SCAN_B + t;
    int v = (gid < n) ? g_cnt[gid] : 0;
    s[t] = v;
    __syncthreads();
    #pragma unroll
    for (int off = 1; off < SCAN_B; off <<= 1) {
        int u = (t >= off) ? s[t - off] : 0;
        __syncthreads();
        s[t] += u;
        __syncthreads();
    }
    if (gid < n) g_rowstart[gid] = s[t] - v;
    if (t == SCAN_B - 1) g_blocksum[blockIdx.x] = s[t];
}

__global__ void scan2_kernel(int nb) {
    __shared__ int s[MAXBLK];
    int t = threadIdx.x;
    int v = (t < nb) ? g_blocksum[t] : 0;
    s[t] = v;
    __syncthreads();
    #pragma unroll
    for (int off = 1; off < MAXBLK; off <<= 1) {
        int u = (t >= off) ? s[t - off] : 0;
        __syncthreads();
        s[t] += u;
        __syncthreads();
    }
    if (t < nb) g_blocksum[t] = s[t] - v;
}

__global__ void scan3_kernel(int n) {
    int gid = blockIdx.x * blockDim.x + threadIdx.x;
    if (gid >= n) return;
    int r = g_rowstart[gid] + g_blocksum[gid >> 10];
    g_rowstart[gid] = r;
    g_cursor[gid] = r;
}

// scatter edges into CSR slots; cnorm finalized inline (dinv ready)
__global__ void build_kernel(const void* __restrict__ ei,
                             const float* __restrict__ ew, int E) {
    int e = blockIdx.x * blockDim.x + threadIdx.x;
    if (e >= E) return;
    int s = edge_src(ei, E, e);
    int d = edge_dst(ei, E, e);
    int pos = atomicAdd(&g_cursor[d], 1);
    g_csrc[pos] = s;
    g_cnorm[pos] = g_dinv[s] * ew[e] * g_dinv[d];
}

// ---------------------------------------------------------------------------
// agg1: one warp per dst node, lanes own float2 of 64 features, 8-deep unroll
// ---------------------------------------------------------------------------
__global__ void agg1_kernel(const float* __restrict__ b1, int n) {
    int warp = (blockIdx.x * blockDim.x + threadIdx.x) >> 5;
    if (warp >= n) return;
    int lane = threadIdx.x & 31;
    const float2* h1 = (const float2*)g_h1;
    int start = g_rowstart[warp];
    int end = start + g_cnt[warp];
    float2 acc = make_float2(0.f, 0.f);

    int j = start;
    for (; j + 8 <= end; j += 8) {
        int   s0 = g_csrc[j],  s1 = g_csrc[j+1],  s2 = g_csrc[j+2],  s3 = g_csrc[j+3];
        int   s4 = g_csrc[j+4], s5 = g_csrc[j+5], s6 = g_csrc[j+6], s7 = g_csrc[j+7];
        float n0 = g_cnorm[j],   n1 = g_cnorm[j+1], n2 = g_cnorm[j+2], n3 = g_cnorm[j+3];
        float n4 = g_cnorm[j+4], n5 = g_cnorm[j+5], n6 = g_cnorm[j+6], n7 = g_cnorm[j+7];
        float2 v0 = h1[(size_t)s0 * 32 + lane];
        float2 v1 = h1[(size_t)s1 * 32 + lane];
        float2 v2 = h1[(size_t)s2 * 32 + lane];
        float2 v3 = h1[(size_t)s3 * 32 + lane];
        float2 v4 = h1[(size_t)s4 * 32 + lane];
        float2 v5 = h1[(size_t)s5 * 32 + lane];
        float2 v6 = h1[(size_t)s6 * 32 + lane];
        float2 v7 = h1[(size_t)s7 * 32 + lane];
        acc.x += n0 * v0.x + n1 * v1.x + n2 * v2.x + n3 * v3.x
               + n4 * v4.x + n5 * v5.x + n6 * v6.x + n7 * v7.x;
        acc.y += n0 * v0.y + n1 * v1.y + n2 * v2.y + n3 * v3.y
               + n4 * v4.y + n5 * v5.y + n6 * v6.y + n7 * v7.y;
    }
    for (; j < end; j++) {
        int s = g_csrc[j];
        float nm = g_cnorm[j];
        float2 v = h1[(size_t)s * 32 + lane];
        acc.x += nm * v.x;
        acc.y += nm * v.y;
    }
    float dv = g_dinv[warp];
    float self = dv * dv;
    float2 hs = h1[(size_t)warp * 32 + lane];
    acc.x += self * hs.x;
    acc.y += self * hs.y;
    acc.x = fmaxf(acc.x + b1[lane * 2 + 0], 0.f);
    acc.y = fmaxf(acc.y + b1[lane * 2 + 1], 0.f);
    ((float2*)g_z)[(size_t)warp * 32 + lane] = acc;
}

// ---------------------------------------------------------------------------
__global__ void gemm2_kernel(const float* __restrict__ W2, int n) {
    __shared__ float sW[FH * FO];
    for (int i = threadIdx.x; i < FH * FO; i += blockDim.x) sW[i] = W2[i];
    __syncthreads();

    int nn = blockIdx.x * blockDim.x + threadIdx.x;
    if (nn >= n) return;
    const float4* z4 = &g_z[(size_t)nn * (FH / 4)];
    float acc[FO];
    #pragma unroll
    for (int j = 0; j < FO; j++) acc[j] = 0.f;
    #pragma unroll
    for (int k4 = 0; k4 < FH / 4; k4++) {
        float4 zv = z4[k4];
        #pragma unroll
        for (int j = 0; j < FO; j++) {
            acc[j] += zv.x * sW[(k4 * 4 + 0) * FO + j];
            acc[j] += zv.y * sW[(k4 * 4 + 1) * FO + j];
            acc[j] += zv.z * sW[(k4 * 4 + 2) * FO + j];
            acc[j] += zv.w * sW[(k4 * 4 + 3) * FO + j];
        }
    }
    float4* o4 = &g_h2[(size_t)nn * (FO / 4)];
    o4[0] = make_float4(acc[0], acc[1], acc[2], acc[3]);
    o4[1] = make_float4(acc[4], acc[5], acc[6], acc[7]);
    o4[2] = make_float4(acc[8], acc[9], acc[10], acc[11]);
    o4[3] = make_float4(acc[12], acc[13], acc[14], acc[15]);
}

// ---------------------------------------------------------------------------
__global__ void agg2_kernel(const float* __restrict__ b2,
                            float* __restrict__ out, int n) {
    int gid = blockIdx.x * blockDim.x + threadIdx.x;
    int node = gid >> 4;
    bool live = node < n;
    if (!live) node = 0;
    int f = gid & 15;
    const float* h2 = (const float*)g_h2;
    int start = g_rowstart[node];
    int end = start + g_cnt[node];
    float acc = 0.f;

    int j = start;
    for (; j + 4 <= end; j += 4) {
        int   s0 = g_csrc[j],  s1 = g_csrc[j+1],  s2 = g_csrc[j+2],  s3 = g_csrc[j+3];
        float n0 = g_cnorm[j], n1 = g_cnorm[j+1], n2 = g_cnorm[j+2], n3 = g_cnorm[j+3];
        acc += n0 * h2[(size_t)s0 * FO + f] + n1 * h2[(size_t)s1 * FO + f]
             + n2 * h2[(size_t)s2 * FO + f] + n3 * h2[(size_t)s3 * FO + f];
    }
    for (; j < end; j++) {
        acc += g_cnorm[j] * h2[(size_t)g_csrc[j] * FO + f];
    }
    float dv = g_dinv[node];
    acc += dv * dv * h2[(size_t)node * FO + f] + b2[f];

    float m = acc;
    #pragma unroll
    for (int off = 8; off > 0; off >>= 1)
        m = fmaxf(m, __shfl_xor_sync(0xffffffffu, m, off));
    float e = expf(acc - m);
    float ssum = e;
    #pragma unroll
    for (int off = 8; off > 0; off >>= 1)
        ssum += __shfl_xor_sync(0xffffffffu, ssum, off);
    if (live) out[(size_t)node * FO + f] = acc - m - logf(ssum);
}

// ---------------------------------------------------------------------------
extern "C" void kernel_launch(void* const* d_in, const int* in_sizes, int n_in,
                              void* d_out, int out_size) {
    const float* x  = (const float*)d_in[0];
    const void*  ei = d_in[1];
    const float* ew = (const float*)d_in[2];
    const float* W1 = (const float*)d_in[3];
    const float* b1 = (const float*)d_in[4];
    const float* W2 = (const float*)d_in[5];
    const float* b2 = (const float*)d_in[6];
    float*       out = (float*)d_out;

    int n = in_sizes[0] / FIN;
    int E = in_sizes[2];

    cudaFuncSetAttribute(gemm1_kernel,
                         cudaFuncAttributeMaxDynamicSharedMemorySize, G1_SMEM);

    probe_kernel<<<1, 1>>>(ei, E, n);
    init_kernel<<<(n + 255) / 256, 256>>>(n);
    cnt_kernel<<<(E + 255) / 256, 256>>>(ei, ew, E);

    // 4th launch -> profiled by ncu
    gemm1_kernel<<<(n + G1_ROWS - 1) / G1_ROWS, G1_THREADS, G1_SMEM>>>(x, W1, n);

    dinv_kernel<<<(n + 255) / 256, 256>>>(n);

    int nb = (n + SCAN_B - 1) / SCAN_B;
    scan1_kernel<<<nb, SCAN_B>>>(n);
    scan2_kernel<<<1, MAXBLK>>>(nb);
    scan3_kernel<<<(n + 255) / 256, 256>>>(n);

    build_kernel<<<(E + 255) / 256, 256>>>(ei, ew, E);

    long long tw = (long long)n * 32;
    agg1_kernel<<<(int)((tw + 255) / 256), 256>>>(b1, n);

    gemm2_kernel<<<(n + 255) / 256, 256>>>(W2, n);

    long long t2 = (long long)n * 16;
    agg2_kernel<<<(int)((t2 + 255) / 256), 256>>>(b2, out, n);
}

// round 11
// speedup vs baseline: 1.2091x; 1.0416x over previous
#include <cuda_runtime.h>
#include <cstdint>

#define MAXN 100000
#define MAXE 1600000
#define FIN 128
#define FH 64
#define FO 16
#define SCAN_B 1024
#define MAXBLK 128
#define G1_ROWS 128
#define G1_THREADS 512
#define G1_SMEM ((FIN * FH + G1_ROWS * FIN) * 4)  // 96KB

// Scratch (device globals: allocation-free)
__device__ int    g_is64;
__device__ float  g_deg[MAXN];
__device__ float  g_dinv[MAXN];
__device__ int    g_cnt[MAXN];
__device__ int    g_rowstart[MAXN];
__device__ int    g_cursor[MAXN];
__device__ int    g_blocksum[MAXBLK];
__device__ int    g_csrc[MAXE];
__device__ float  g_cnorm[MAXE];
__device__ float4 g_h1[(size_t)MAXN * (FH / 4)];
__device__ float4 g_z [(size_t)MAXN * (FH / 4)];
__device__ float4 g_h2[(size_t)MAXN * (FO / 4)];

__device__ __forceinline__ int edge_src(const void* ei, int E, int e) {
    return g_is64 ? (int)((const long long*)ei)[e] : ((const int*)ei)[e];
}
__device__ __forceinline__ int edge_dst(const void* ei, int E, int e) {
    return g_is64 ? (int)((const long long*)ei)[(size_t)E + e]
                  : ((const int*)ei)[(size_t)E + e];
}

// ---------------------------------------------------------------------------
__global__ void probe_kernel(const void* ei, int E, int n) {
    if (threadIdx.x != 0 || blockIdx.x != 0) return;
    const long long* p = (const long long*)ei;
    int ok64 = 1;
    int m = E < 64 ? E : 64;
    for (int i = 0; i < m; i++) {
        long long v = p[i];
        long long w = p[(size_t)E + i];
        if (v < 0 || v >= n || w < 0 || w >= n) { ok64 = 0; break; }
    }
    g_is64 = ok64;
}

__global__ void init_kernel(int n) {
    int i = blockIdx.x * blockDim.x + threadIdx.x;
    if (i < n) { g_cnt[i] = 0; g_deg[i] = 1.0f; }   // self-loop weight 1
}

// fused: edge count (int atomic) + weighted in-degree (float atomic)
__global__ void cnt_kernel(const void* __restrict__ ei,
                           const float* __restrict__ ew, int E) {
    int e = blockIdx.x * blockDim.x + threadIdx.x;
    if (e >= E) return;
    int d = edge_dst(ei, E, e);
    atomicAdd(&g_cnt[d], 1);
    atomicAdd(&g_deg[d], ew[e]);
}

// ---------------------------------------------------------------------------
// h1 = x @ W1, FFMA2 + 2-column thread tile, 2 blocks/SM.
// ---------------------------------------------------------------------------
__global__ void __launch_bounds__(G1_THREADS, 2)
gemm1_kernel(const float* __restrict__ x,
             const float* __restrict__ W1, int n) {
    extern __shared__ float smem[];
    float* sWt = smem;               // 64 cols x 128 k (swizzled f4 units)
    float* sx  = smem + FIN * FH;    // 128 rows x 128 k, linear
    int t = threadIdx.x;

    #pragma unroll
    for (int i = t; i < FIN * FH; i += G1_THREADS) {
        int k = i >> 6, col = i & 63;
        int unit = col * 32 + ((k >> 2) ^ (col & 31));
        sWt[unit * 4 + (k & 3)] = W1[i];
    }

    int rowBase = blockIdx.x * G1_ROWS;
    #pragma unroll
    for (int i = t; i < G1_ROWS * FIN / 4; i += G1_THREADS) {
        int r = i / (FIN / 4), c = i % (FIN / 4);
        int row = rowBase + r;
        float4 val = (row < n) ? ((const float4*)(x + (size_t)row * FIN))[c]
                               : make_float4(0.f, 0.f, 0.f, 0.f);
        ((float4*)(sx + r * FIN))[c] = val;
    }
    __syncthreads();

    int cp = t & 31;
    int rg = t >> 5;

    uint32_t wbase = (uint32_t)__cvta_generic_to_shared(sWt);
    uint32_t xbase = (uint32_t)__cvta_generic_to_shared(sx + (rg * 8) * FIN);

    uint64_t accA[8], accB[8];
    #pragma unroll
    for (int i = 0; i < 8; i++) { accA[i] = 0ull; accB[i] = 0ull; }

    #pragma unroll
    for (int k4 = 0; k4 < FIN / 4; k4++) {
        int sw = k4 ^ cp;
        uint64_t wA01, wA23, wB01, wB23;
        uint32_t waddrA = wbase + (uint32_t)((cp * 32 + sw) * 16);
        uint32_t waddrB = waddrA + (uint32_t)(32 * 32 * 16);
        asm volatile("ld.shared.v2.b64 {%0, %1}, [%2];"
                     : "=l"(wA01), "=l"(wA23) : "r"(waddrA));
        asm volatile("ld.shared.v2.b64 {%0, %1}, [%2];"
                     : "=l"(wB01), "=l"(wB23) : "r"(waddrB));
        #pragma unroll
        for (int i = 0; i < 8; i++) {
            uint64_t x01, x23;
            uint32_t xaddr = xbase + (uint32_t)(i * FIN * 4 + k4 * 16);
            asm volatile("ld.shared.v2.b64 {%0, %1}, [%2];"
                         : "=l"(x01), "=l"(x23) : "r"(xaddr));
            asm volatile("fma.rn.f32x2 %0, %1, %2, %0;"
                         : "+l"(accA[i]) : "l"(x01), "l"(wA01));
            asm volatile("fma.rn.f32x2 %0, %1, %2, %0;"
                         : "+l"(accA[i]) : "l"(x23), "l"(wA23));
            asm volatile("fma.rn.f32x2 %0, %1, %2, %0;"
                         : "+l"(accB[i]) : "l"(x01), "l"(wB01));
            asm volatile("fma.rn.f32x2 %0, %1, %2, %0;"
                         : "+l"(accB[i]) : "l"(x23), "l"(wB23));
        }
    }

    float* h1 = (float*)g_h1;
    #pragma unroll
    for (int i = 0; i < 8; i++) {
        int row = rowBase + rg * 8 + i;
        if (row < n) {
            float a = __uint_as_float((uint32_t)(accA[i] & 0xffffffffull))
                    + __uint_as_float((uint32_t)(accA[i] >> 32));
            float b = __uint_as_float((uint32_t)(accB[i] & 0xffffffffull))
                    + __uint_as_float((uint32_t)(accB[i] >> 32));
            h1[(size_t)row * FH + cp]      = a;
            h1[(size_t)row * FH + cp + 32] = b;
        }
    }
}

// ---------------------------------------------------------------------------
__global__ void dinv_kernel(int n) {
    int i = blockIdx.x * blockDim.x + threadIdx.x;
    if (i < n) g_dinv[i] = rsqrtf(g_deg[i]);
}

__global__ void scan1_kernel(int n) {
    __shared__ int s[SCAN_B];
    int t = threadIdx.x;
    int gid = blockIdx.x * SCAN_B + t;
    int v = (gid < n) ? g_cnt[gid] : 0;
    s[t] = v;
    __syncthreads();
    #pragma unroll
    for (int off = 1; off < SCAN_B; off <<= 1) {
        int u = (t >= off) ? s[t - off] : 0;
        __syncthreads();
        s[t] += u;
        __syncthreads();
    }
    if (gid < n) g_rowstart[gid] = s[t] - v;
    if (t == SCAN_B - 1) g_blocksum[blockIdx.x] = s[t];
}

__global__ void scan2_kernel(int nb) {
    __shared__ int s[MAXBLK];
    int t = threadIdx.x;
    int v = (t < nb) ? g_blocksum[t] : 0;
    s[t] = v;
    __syncthreads();
    #pragma unroll
    for (int off = 1; off < MAXBLK; off <<= 1) {
        int u = (t >= off) ? s[t - off] : 0;
        __syncthreads();
        s[t] += u;
        __syncthreads();
    }
    if (t < nb) g_blocksum[t] = s[t] - v;
}

__global__ void scan3_kernel(int n) {
    int gid = blockIdx.x * blockDim.x + threadIdx.x;
    if (gid >= n) return;
    int r = g_rowstart[gid] + g_blocksum[gid >> 10];
    g_rowstart[gid] = r;
    g_cursor[gid] = r;
}

__global__ void build_kernel(const void* __restrict__ ei,
                             const float* __restrict__ ew, int E) {
    int e = blockIdx.x * blockDim.x + threadIdx.x;
    if (e >= E) return;
    int s = edge_src(ei, E, e);
    int d = edge_dst(ei, E, e);
    int pos = atomicAdd(&g_cursor[d], 1);
    g_csrc[pos] = s;
    g_cnorm[pos] = g_dinv[s] * ew[e] * g_dinv[d];
}

// ---------------------------------------------------------------------------
__global__ void agg1_kernel(const float* __restrict__ b1, int n) {
    int warp = (blockIdx.x * blockDim.x + threadIdx.x) >> 5;
    if (warp >= n) return;
    int lane = threadIdx.x & 31;
    const float2* h1 = (const float2*)g_h1;
    int start = g_rowstart[warp];
    int end = start + g_cnt[warp];
    float2 acc = make_float2(0.f, 0.f);

    int j = start;
    for (; j + 8 <= end; j += 8) {
        int   s0 = g_csrc[j],  s1 = g_csrc[j+1],  s2 = g_csrc[j+2],  s3 = g_csrc[j+3];
        int   s4 = g_csrc[j+4], s5 = g_csrc[j+5], s6 = g_csrc[j+6], s7 = g_csrc[j+7];
        float n0 = g_cnorm[j],   n1 = g_cnorm[j+1], n2 = g_cnorm[j+2], n3 = g_cnorm[j+3];
        float n4 = g_cnorm[j+4], n5 = g_cnorm[j+5], n6 = g_cnorm[j+6], n7 = g_cnorm[j+7];
        float2 v0 = h1[(size_t)s0 * 32 + lane];
        float2 v1 = h1[(size_t)s1 * 32 + lane];
        float2 v2 = h1[(size_t)s2 * 32 + lane];
        float2 v3 = h1[(size_t)s3 * 32 + lane];
        float2 v4 = h1[(size_t)s4 * 32 + lane];
        float2 v5 = h1[(size_t)s5 * 32 + lane];
        float2 v6 = h1[(size_t)s6 * 32 + lane];
        float2 v7 = h1[(size_t)s7 * 32 + lane];
        acc.x += n0 * v0.x + n1 * v1.x + n2 * v2.x + n3 * v3.x
               + n4 * v4.x + n5 * v5.x + n6 * v6.x + n7 * v7.x;
        acc.y += n0 * v0.y + n1 * v1.y + n2 * v2.y + n3 * v3.y
               + n4 * v4.y + n5 * v5.y + n6 * v6.y + n7 * v7.y;
    }
    for (; j < end; j++) {
        int s = g_csrc[j];
        float nm = g_cnorm[j];
        float2 v = h1[(size_t)s * 32 + lane];
        acc.x += nm * v.x;
        acc.y += nm * v.y;
    }
    float dv = g_dinv[warp];
    float self = dv * dv;
    float2 hs = h1[(size_t)warp * 32 + lane];
    acc.x += self * hs.x;
    acc.y += self * hs.y;
    acc.x = fmaxf(acc.x + b1[lane * 2 + 0], 0.f);
    acc.y = fmaxf(acc.y + b1[lane * 2 + 1], 0.f);
    ((float2*)g_z)[(size_t)warp * 32 + lane] = acc;
}

// ---------------------------------------------------------------------------
__global__ void gemm2_kernel(const float* __restrict__ W2, int n) {
    __shared__ float sW[FH * FO];
    for (int i = threadIdx.x; i < FH * FO; i += blockDim.x) sW[i] = W2[i];
    __syncthreads();

    int nn = blockIdx.x * blockDim.x + threadIdx.x;
    if (nn >= n) return;
    const float4* z4 = &g_z[(size_t)nn * (FH / 4)];
    float acc[FO];
    #pragma unroll
    for (int j = 0; j < FO; j++) acc[j] = 0.f;
    #pragma unroll
    for (int k4 = 0; k4 < FH / 4; k4++) {
        float4 zv = z4[k4];
        #pragma unroll
        for (int j = 0; j < FO; j++) {
            acc[j] += zv.x * sW[(k4 * 4 + 0) * FO + j];
            acc[j] += zv.y * sW[(k4 * 4 + 1) * FO + j];
            acc[j] += zv.z * sW[(k4 * 4 + 2) * FO + j];
            acc[j] += zv.w * sW[(k4 * 4 + 3) * FO + j];
        }
    }
    float4* o4 = &g_h2[(size_t)nn * (FO / 4)];
    o4[0] = make_float4(acc[0], acc[1], acc[2], acc[3]);
    o4[1] = make_float4(acc[4], acc[5], acc[6], acc[7]);
    o4[2] = make_float4(acc[8], acc[9], acc[10], acc[11]);
    o4[3] = make_float4(acc[12], acc[13], acc[14], acc[15]);
}

// ---------------------------------------------------------------------------
__global__ void agg2_kernel(const float* __restrict__ b2,
                            float* __restrict__ out, int n) {
    int gid = blockIdx.x * blockDim.x + threadIdx.x;
    int node = gid >> 4;
    bool live = node < n;
    if (!live) node = 0;
    int f = gid & 15;
    const float* h2 = (const float*)g_h2;
    int start = g_rowstart[node];
    int end = start + g_cnt[node];
    float acc = 0.f;

    int j = start;
    for (; j + 4 <= end; j += 4) {
        int   s0 = g_csrc[j],  s1 = g_csrc[j+1],  s2 = g_csrc[j+2],  s3 = g_csrc[j+3];
        float n0 = g_cnorm[j], n1 = g_cnorm[j+1], n2 = g_cnorm[j+2], n3 = g_cnorm[j+3];
        acc += n0 * h2[(size_t)s0 * FO + f] + n1 * h2[(size_t)s1 * FO + f]
             + n2 * h2[(size_t)s2 * FO + f] + n3 * h2[(size_t)s3 * FO + f];
    }
    for (; j < end; j++) {
        acc += g_cnorm[j] * h2[(size_t)g_csrc[j] * FO + f];
    }
    float dv = g_dinv[node];
    acc += dv * dv * h2[(size_t)node * FO + f] + b2[f];

    float m = acc;
    #pragma unroll
    for (int off = 8; off > 0; off >>= 1)
        m = fmaxf(m, __shfl_xor_sync(0xffffffffu, m, off));
    float e = expf(acc - m);
    float ssum = e;
    #pragma unroll
    for (int off = 8; off > 0; off >>= 1)
        ssum += __shfl_xor_sync(0xffffffffu, ssum, off);
    if (live) out[(size_t)node * FO + f] = acc - m - logf(ssum);
}

// ---------------------------------------------------------------------------
extern "C" void kernel_launch(void* const* d_in, const int* in_sizes, int n_in,
                              void* d_out, int out_size) {
    const float* x  = (const float*)d_in[0];
    const void*  ei = d_in[1];
    const float* ew = (const float*)d_in[2];
    const float* W1 = (const float*)d_in[3];
    const float* b1 = (const float*)d_in[4];
    const float* W2 = (const float*)d_in[5];
    const float* b2 = (const float*)d_in[6];
    float*       out = (float*)d_out;

    int n = in_sizes[0] / FIN;
    int E = in_sizes[2];

    // One-time resources (no device memory; identical captured work per call)
    static cudaStream_t s1 = nullptr;
    static cudaEvent_t evFork = nullptr, evJoin = nullptr;
    static bool inited = false;
    if (!inited) {
        cudaStreamCreateWithFlags(&s1, cudaStreamNonBlocking);
        cudaEventCreateWithFlags(&evFork, cudaEventDisableTiming);
        cudaEventCreateWithFlags(&evJoin, cudaEventDisableTiming);
        cudaFuncSetAttribute(gemm1_kernel,
                             cudaFuncAttributeMaxDynamicSharedMemorySize, G1_SMEM);
        inited = true;
    }

    // main stream (legacy default): CSR chain
    probe_kernel<<<1, 1>>>(ei, E, n);
    init_kernel<<<(n + 255) / 256, 256>>>(n);
    cnt_kernel<<<(E + 255) / 256, 256>>>(ei, ew, E);

    // fork: gemm1 on side stream, concurrent with CSR chain (4th launch -> ncu)
    cudaEventRecord(evFork, 0);
    cudaStreamWaitEvent(s1, evFork, 0);
    gemm1_kernel<<<(n + G1_ROWS - 1) / G1_ROWS, G1_THREADS, G1_SMEM, s1>>>(x, W1, n);
    cudaEventRecord(evJoin, s1);

    dinv_kernel<<<(n + 255) / 256, 256>>>(n);

    int nb = (n + SCAN_B - 1) / SCAN_B;
    scan1_kernel<<<nb, SCAN_B>>>(n);
    scan2_kernel<<<1, MAXBLK>>>(nb);
    scan3_kernel<<<(n + 255) / 256, 256>>>(n);

    build_kernel<<<(E + 255) / 256, 256>>>(ei, ew, E);

    // join: agg1 needs both h1 (side stream) and CSR (main stream)
    cudaStreamWaitEvent(0, evJoin, 0);

    long long tw = (long long)n * 32;
    agg1_kernel<<<(int)((tw + 255) / 256), 256>>>(b1, n);

    gemm2_kernel<<<(n + 255) / 256, 256>>>(W2, n);

    long long t2 = (long long)n * 16;
    agg2_kernel<<<(int)((t2 + 255) / 256), 256>>>(b2, out, n);
}

// round 12
// speedup vs baseline: 1.2469x; 1.0313x over previous
#include <cuda_runtime.h>
#include <cstdint>

#define MAXN 100000
#define MAXE 1600000
#define FIN 128
#define FH 64
#define FO 16
#define SCAN_B 1024
#define MAXBLK 128
#define G1_ROWS 128
#define G1_THREADS 512
#define G1_SMEM ((FIN * FH + G1_ROWS * FIN) * 4)  // 96KB

// Scratch (device globals: allocation-free)
__device__ int    g_is64;
__device__ float  g_deg[MAXN];
__device__ float  g_dinv[MAXN];
__device__ int    g_cnt[MAXN];
__device__ int    g_rowstart[MAXN];
__device__ int    g_cursor[MAXN];
__device__ int    g_blocksum[MAXBLK];
__device__ int2   g_edge[MAXE];      // {src, norm-as-int-bits} per CSR slot
__device__ float4 g_h1[(size_t)MAXN * (FH / 4)];
__device__ float4 g_z [(size_t)MAXN * (FH / 4)];
__device__ float4 g_h2[(size_t)MAXN * (FO / 4)];

__device__ __forceinline__ int edge_src(const void* ei, int E, int e) {
    return g_is64 ? (int)((const long long*)ei)[e] : ((const int*)ei)[e];
}
__device__ __forceinline__ int edge_dst(const void* ei, int E, int e) {
    return g_is64 ? (int)((const long long*)ei)[(size_t)E + e]
                  : ((const int*)ei)[(size_t)E + e];
}

// ---------------------------------------------------------------------------
__global__ void probe_kernel(const void* ei, int E, int n) {
    if (threadIdx.x != 0 || blockIdx.x != 0) return;
    const long long* p = (const long long*)ei;
    int ok64 = 1;
    int m = E < 64 ? E : 64;
    for (int i = 0; i < m; i++) {
        long long v = p[i];
        long long w = p[(size_t)E + i];
        if (v < 0 || v >= n || w < 0 || w >= n) { ok64 = 0; break; }
    }
    g_is64 = ok64;
}

__global__ void init_kernel(int n) {
    int i = blockIdx.x * blockDim.x + threadIdx.x;
    if (i < n) { g_cnt[i] = 0; g_deg[i] = 1.0f; }   // self-loop weight 1
}

// fused: edge count (int atomic) + weighted in-degree (float atomic)
__global__ void cnt_kernel(const void* __restrict__ ei,
                           const float* __restrict__ ew, int E) {
    int e = blockIdx.x * blockDim.x + threadIdx.x;
    if (e >= E) return;
    int d = edge_dst(ei, E, e);
    atomicAdd(&g_cnt[d], 1);
    atomicAdd(&g_deg[d], ew[e]);
}

// ---------------------------------------------------------------------------
// h1 = x @ W1, FFMA2 + 2-column thread tile, 2 blocks/SM.
// ---------------------------------------------------------------------------
__global__ void __launch_bounds__(G1_THREADS, 2)
gemm1_kernel(const float* __restrict__ x,
             const float* __restrict__ W1, int n) {
    extern __shared__ float smem[];
    float* sWt = smem;               // 64 cols x 128 k (swizzled f4 units)
    float* sx  = smem + FIN * FH;    // 128 rows x 128 k, linear
    int t = threadIdx.x;

    #pragma unroll
    for (int i = t; i < FIN * FH; i += G1_THREADS) {
        int k = i >> 6, col = i & 63;
        int unit = col * 32 + ((k >> 2) ^ (col & 31));
        sWt[unit * 4 + (k & 3)] = W1[i];
    }

    int rowBase = blockIdx.x * G1_ROWS;
    #pragma unroll
    for (int i = t; i < G1_ROWS * FIN / 4; i += G1_THREADS) {
        int r = i / (FIN / 4), c = i % (FIN / 4);
        int row = rowBase + r;
        float4 val = (row < n) ? ((const float4*)(x + (size_t)row * FIN))[c]
                               : make_float4(0.f, 0.f, 0.f, 0.f);
        ((float4*)(sx + r * FIN))[c] = val;
    }
    __syncthreads();

    int cp = t & 31;
    int rg = t >> 5;

    uint32_t wbase = (uint32_t)__cvta_generic_to_shared(sWt);
    uint32_t xbase = (uint32_t)__cvta_generic_to_shared(sx + (rg * 8) * FIN);

    uint64_t accA[8], accB[8];
    #pragma unroll
    for (int i = 0; i < 8; i++) { accA[i] = 0ull; accB[i] = 0ull; }

    #pragma unroll
    for (int k4 = 0; k4 < FIN / 4; k4++) {
        int sw = k4 ^ cp;
        uint64_t wA01, wA23, wB01, wB23;
        uint32_t waddrA = wbase + (uint32_t)((cp * 32 + sw) * 16);
        uint32_t waddrB = waddrA + (uint32_t)(32 * 32 * 16);
        asm volatile("ld.shared.v2.b64 {%0, %1}, [%2];"
                     : "=l"(wA01), "=l"(wA23) : "r"(waddrA));
        asm volatile("ld.shared.v2.b64 {%0, %1}, [%2];"
                     : "=l"(wB01), "=l"(wB23) : "r"(waddrB));
        #pragma unroll
        for (int i = 0; i < 8; i++) {
            uint64_t x01, x23;
            uint32_t xaddr = xbase + (uint32_t)(i * FIN * 4 + k4 * 16);
            asm volatile("ld.shared.v2.b64 {%0, %1}, [%2];"
                         : "=l"(x01), "=l"(x23) : "r"(xaddr));
            asm volatile("fma.rn.f32x2 %0, %1, %2, %0;"
                         : "+l"(accA[i]) : "l"(x01), "l"(wA01));
            asm volatile("fma.rn.f32x2 %0, %1, %2, %0;"
                         : "+l"(accA[i]) : "l"(x23), "l"(wA23));
            asm volatile("fma.rn.f32x2 %0, %1, %2, %0;"
                         : "+l"(accB[i]) : "l"(x01), "l"(wB01));
            asm volatile("fma.rn.f32x2 %0, %1, %2, %0;"
                         : "+l"(accB[i]) : "l"(x23), "l"(wB23));
        }
    }

    float* h1 = (float*)g_h1;
    #pragma unroll
    for (int i = 0; i < 8; i++) {
        int row = rowBase + rg * 8 + i;
        if (row < n) {
            float a = __uint_as_float((uint32_t)(accA[i] & 0xffffffffull))
                    + __uint_as_float((uint32_t)(accA[i] >> 32));
            float b = __uint_as_float((uint32_t)(accB[i] & 0xffffffffull))
                    + __uint_as_float((uint32_t)(accB[i] >> 32));
            h1[(size_t)row * FH + cp]      = a;
            h1[(size_t)row * FH + cp + 32] = b;
        }
    }
}

// ---------------------------------------------------------------------------
// scan1: per-block inclusive scan + fused dinv = rsqrt(deg)
// ---------------------------------------------------------------------------
__global__ void scan1_kernel(int n) {
    __shared__ int s[SCAN_B];
    int t = threadIdx.x;
    int gid = blockIdx.x * SCAN_B + t;
    int v = (gid < n) ? g_cnt[gid] : 0;
    s[t] = v;
    if (gid < n) g_dinv[gid] = rsqrtf(g_deg[gid]);   // fused
    __syncthreads();
    #pragma unroll
    for (int off = 1; off < SCAN_B; off <<= 1) {
        int u = (t >= off) ? s[t - off] : 0;
        __syncthreads();
        s[t] += u;
        __syncthreads();
    }
    if (gid < n) g_rowstart[gid] = s[t] - v;
    if (t == SCAN_B - 1) g_blocksum[blockIdx.x] = s[t];
}

__global__ void scan2_kernel(int nb) {
    __shared__ int s[MAXBLK];
    int t = threadIdx.x;
    int v = (t < nb) ? g_blocksum[t] : 0;
    s[t] = v;
    __syncthreads();
    #pragma unroll
    for (int off = 1; off < MAXBLK; off <<= 1) {
        int u = (t >= off) ? s[t - off] : 0;
        __syncthreads();
        s[t] += u;
        __syncthreads();
    }
    if (t < nb) g_blocksum[t] = s[t] - v;
}

__global__ void scan3_kernel(int n) {
    int gid = blockIdx.x * blockDim.x + threadIdx.x;
    if (gid >= n) return;
    int r = g_rowstart[gid] + g_blocksum[gid >> 10];
    g_rowstart[gid] = r;
    g_cursor[gid] = r;
}

// scatter edges into CSR slots; one 8B store per edge
__global__ void build_kernel(const void* __restrict__ ei,
                             const float* __restrict__ ew, int E) {
    int e = blockIdx.x * blockDim.x + threadIdx.x;
    if (e >= E) return;
    int s = edge_src(ei, E, e);
    int d = edge_dst(ei, E, e);
    int pos = atomicAdd(&g_cursor[d], 1);
    float nm = g_dinv[s] * ew[e] * g_dinv[d];
    g_edge[pos] = make_int2(s, __float_as_int(nm));
}

// ---------------------------------------------------------------------------
// agg1: one warp per dst node, lanes own float2 of 64 features, 8-deep unroll
// ---------------------------------------------------------------------------
__global__ void agg1_kernel(const float* __restrict__ b1, int n) {
    int warp = (blockIdx.x * blockDim.x + threadIdx.x) >> 5;
    if (warp >= n) return;
    int lane = threadIdx.x & 31;
    const float2* h1 = (const float2*)g_h1;
    int start = g_rowstart[warp];
    int end = start + g_cnt[warp];
    float2 acc = make_float2(0.f, 0.f);

    int j = start;
    for (; j + 8 <= end; j += 8) {
        int2 e0 = g_edge[j],   e1 = g_edge[j+1], e2 = g_edge[j+2], e3 = g_edge[j+3];
        int2 e4 = g_edge[j+4], e5 = g_edge[j+5], e6 = g_edge[j+6], e7 = g_edge[j+7];
        float2 v0 = h1[(size_t)e0.x * 32 + lane];
        float2 v1 = h1[(size_t)e1.x * 32 + lane];
        float2 v2 = h1[(size_t)e2.x * 32 + lane];
        float2 v3 = h1[(size_t)e3.x * 32 + lane];
        float2 v4 = h1[(size_t)e4.x * 32 + lane];
        float2 v5 = h1[(size_t)e5.x * 32 + lane];
        float2 v6 = h1[(size_t)e6.x * 32 + lane];
        float2 v7 = h1[(size_t)e7.x * 32 + lane];
        float n0 = __int_as_float(e0.y), n1 = __int_as_float(e1.y);
        float n2 = __int_as_float(e2.y), n3 = __int_as_float(e3.y);
        float n4 = __int_as_float(e4.y), n5 = __int_as_float(e5.y);
        float n6 = __int_as_float(e6.y), n7 = __int_as_float(e7.y);
        acc.x += n0 * v0.x + n1 * v1.x + n2 * v2.x + n3 * v3.x
               + n4 * v4.x + n5 * v5.x + n6 * v6.x + n7 * v7.x;
        acc.y += n0 * v0.y + n1 * v1.y + n2 * v2.y + n3 * v3.y
               + n4 * v4.y + n5 * v5.y + n6 * v6.y + n7 * v7.y;
    }
    for (; j < end; j++) {
        int2 e = g_edge[j];
        float nm = __int_as_float(e.y);
        float2 v = h1[(size_t)e.x * 32 + lane];
        acc.x += nm * v.x;
        acc.y += nm * v.y;
    }
    float dv = g_dinv[warp];
    float self = dv * dv;
    float2 hs = h1[(size_t)warp * 32 + lane];
    acc.x += self * hs.x;
    acc.y += self * hs.y;
    acc.x = fmaxf(acc.x + b1[lane * 2 + 0], 0.f);
    acc.y = fmaxf(acc.y + b1[lane * 2 + 1], 0.f);
    ((float2*)g_z)[(size_t)warp * 32 + lane] = acc;
}

// ---------------------------------------------------------------------------
__global__ void gemm2_kernel(const float* __restrict__ W2, int n) {
    __shared__ float sW[FH * FO];
    for (int i = threadIdx.x; i < FH * FO; i += blockDim.x) sW[i] = W2[i];
    __syncthreads();

    int nn = blockIdx.x * blockDim.x + threadIdx.x;
    if (nn >= n) return;
    const float4* z4 = &g_z[(size_t)nn * (FH / 4)];
    float acc[FO];
    #pragma unroll
    for (int j = 0; j < FO; j++) acc[j] = 0.f;
    #pragma unroll
    for (int k4 = 0; k4 < FH / 4; k4++) {
        float4 zv = z4[k4];
        #pragma unroll
        for (int j = 0; j < FO; j++) {
            acc[j] += zv.x * sW[(k4 * 4 + 0) * FO + j];
            acc[j] += zv.y * sW[(k4 * 4 + 1) * FO + j];
            acc[j] += zv.z * sW[(k4 * 4 + 2) * FO + j];
            acc[j] += zv.w * sW[(k4 * 4 + 3) * FO + j];
        }
    }
    float4* o4 = &g_h2[(size_t)nn * (FO / 4)];
    o4[0] = make_float4(acc[0], acc[1], acc[2], acc[3]);
    o4[1] = make_float4(acc[4], acc[5], acc[6], acc[7]);
    o4[2] = make_float4(acc[8], acc[9], acc[10], acc[11]);
    o4[3] = make_float4(acc[12], acc[13], acc[14], acc[15]);
}

// ---------------------------------------------------------------------------
__global__ void agg2_kernel(const float* __restrict__ b2,
                            float* __restrict__ out, int n) {
    int gid = blockIdx.x * blockDim.x + threadIdx.x;
    int node = gid >> 4;
    bool live = node < n;
    if (!live) node = 0;
    int f = gid & 15;
    const float* h2 = (const float*)g_h2;
    int start = g_rowstart[node];
    int end = start + g_cnt[node];
    float acc = 0.f;

    int j = start;
    for (; j + 4 <= end; j += 4) {
        int2 e0 = g_edge[j],   e1 = g_edge[j+1];
        int2 e2 = g_edge[j+2], e3 = g_edge[j+3];
        acc += __int_as_float(e0.y) * h2[(size_t)e0.x * FO + f]
             + __int_as_float(e1.y) * h2[(size_t)e1.x * FO + f]
             + __int_as_float(e2.y) * h2[(size_t)e2.x * FO + f]
             + __int_as_float(e3.y) * h2[(size_t)e3.x * FO + f];
    }
    for (; j < end; j++) {
        int2 e = g_edge[j];
        acc += __int_as_float(e.y) * h2[(size_t)e.x * FO + f];
    }
    float dv = g_dinv[node];
    acc += dv * dv * h2[(size_t)node * FO + f] + b2[f];

    float m = acc;
    #pragma unroll
    for (int off = 8; off > 0; off >>= 1)
        m = fmaxf(m, __shfl_xor_sync(0xffffffffu, m, off));
    float e = expf(acc - m);
    float ssum = e;
    #pragma unroll
    for (int off = 8; off > 0; off >>= 1)
        ssum += __shfl_xor_sync(0xffffffffu, ssum, off);
    if (live) out[(size_t)node * FO + f] = acc - m - logf(ssum);
}

// ---------------------------------------------------------------------------
extern "C" void kernel_launch(void* const* d_in, const int* in_sizes, int n_in,
                              void* d_out, int out_size) {
    const float* x  = (const float*)d_in[0];
    const void*  ei = d_in[1];
    const float* ew = (const float*)d_in[2];
    const float* W1 = (const float*)d_in[3];
    const float* b1 = (const float*)d_in[4];
    const float* W2 = (const float*)d_in[5];
    const float* b2 = (const float*)d_in[6];
    float*       out = (float*)d_out;

    int n = in_sizes[0] / FIN;
    int E = in_sizes[2];

    static cudaStream_t s1 = nullptr;
    static cudaEvent_t evFork = nullptr, evJoin = nullptr;
    static bool inited = false;
    if (!inited) {
        cudaStreamCreateWithFlags(&s1, cudaStreamNonBlocking);
        cudaEventCreateWithFlags(&evFork, cudaEventDisableTiming);
        cudaEventCreateWithFlags(&evJoin, cudaEventDisableTiming);
        cudaFuncSetAttribute(gemm1_kernel,
                             cudaFuncAttributeMaxDynamicSharedMemorySize, G1_SMEM);
        inited = true;
    }

    // fork FIRST: gemm1 overlaps the entire CSR chain
    cudaEventRecord(evFork, 0);
    cudaStreamWaitEvent(s1, evFork, 0);
    gemm1_kernel<<<(n + G1_ROWS - 1) / G1_ROWS, G1_THREADS, G1_SMEM, s1>>>(x, W1, n);
    cudaEventRecord(evJoin, s1);

    // main stream: CSR chain  (4th kernel launch overall = cnt -> ncu)
    probe_kernel<<<1, 1>>>(ei, E, n);
    init_kernel<<<(n + 255) / 256, 256>>>(n);
    cnt_kernel<<<(E + 255) / 256, 256>>>(ei, ew, E);

    int nb = (n + SCAN_B - 1) / SCAN_B;
    scan1_kernel<<<nb, SCAN_B>>>(n);
    scan2_kernel<<<1, MAXBLK>>>(nb);
    scan3_kernel<<<(n + 255) / 256, 256>>>(n);

    build_kernel<<<(E + 255) / 256, 256>>>(ei, ew, E);

    // join: agg1 needs h1 (side stream) and CSR (main stream)
    cudaStreamWaitEvent(0, evJoin, 0);

    long long tw = (long long)n * 32;
    agg1_kernel<<<(int)((tw + 255) / 256), 256>>>(b1, n);

    gemm2_kernel<<<(n + 255) / 256, 256>>>(W2, n);

    long long t2 = (long long)n * 16;
    agg2_kernel<<<(int)((t2 + 255) / 256), 256>>>(b2, out, n);
}

// round 13
// speedup vs baseline: 1.3386x; 1.0736x over previous
#include <cuda_runtime.h>
#include <cuda_fp16.h>
#include <cstdint>

#define MAXN 100000
#define MAXE 1600000
#define FIN 128
#define FH 64
#define FO 16
#define SCAN_B 1024
#define MAXBLK 128
#define G1_ROWS 128
#define G1_THREADS 512
#define G1_SMEM ((FIN * FH + G1_ROWS * FIN) * 4)  // 96KB

// Scratch (device globals: allocation-free)
__device__ int                g_is64;
__device__ unsigned long long g_packed[MAXN];   // count<<40 | deg_fixed(2^-24)
__device__ float              g_dinv[MAXN];
__device__ int                g_cnt[MAXN];
__device__ int                g_rowstart[MAXN];
__device__ int                g_cursor[MAXN];
__device__ int                g_blocksum[MAXBLK];
__device__ int2               g_edge[MAXE];     // {src, norm bits}
__device__ __half2            g_h1h[(size_t)MAXN * (FH / 2)];  // fp16 h1 [n][64]
__device__ float4             g_z [(size_t)MAXN * (FH / 4)];
__device__ float4             g_h2[(size_t)MAXN * (FO / 4)];

__device__ __forceinline__ int edge_src(const void* ei, int E, int e) {
    return g_is64 ? (int)((const long long*)ei)[e] : ((const int*)ei)[e];
}
__device__ __forceinline__ int edge_dst(const void* ei, int E, int e) {
    return g_is64 ? (int)((const long long*)ei)[(size_t)E + e]
                  : ((const int*)ei)[(size_t)E + e];
}

// ---------------------------------------------------------------------------
__global__ void probe_kernel(const void* ei, int E, int n) {
    if (threadIdx.x != 0 || blockIdx.x != 0) return;
    const long long* p = (const long long*)ei;
    int ok64 = 1;
    int m = E < 64 ? E : 64;
    for (int i = 0; i < m; i++) {
        long long v = p[i];
        long long w = p[(size_t)E + i];
        if (v < 0 || v >= n || w < 0 || w >= n) { ok64 = 0; break; }
    }
    g_is64 = ok64;
}

__global__ void init_kernel(int n) {
    int i = blockIdx.x * blockDim.x + threadIdx.x;
    if (i < n) g_packed[i] = (unsigned long long)1 << 24;  // deg = 1.0 fixed
}

// ONE 64-bit atomic per edge: +1 in count field, +ew (fixed point) in deg field
__global__ void cnt_kernel(const void* __restrict__ ei,
                           const float* __restrict__ ew, int E) {
    int e = blockIdx.x * blockDim.x + threadIdx.x;
    if (e >= E) return;
    int d = edge_dst(ei, E, e);
    unsigned long long add =
        ((unsigned long long)1 << 40) +
        (unsigned long long)__float2uint_rn(ew[e] * 16777216.0f);
    atomicAdd(&g_packed[d], add);
}

// ---------------------------------------------------------------------------
// h1 = x @ W1, FFMA2 + 2-column thread tile, 2 blocks/SM. fp16 output.
// ---------------------------------------------------------------------------
__global__ void __launch_bounds__(G1_THREADS, 2)
gemm1_kernel(const float* __restrict__ x,
             const float* __restrict__ W1, int n) {
    extern __shared__ float smem[];
    float* sWt = smem;               // 64 cols x 128 k (swizzled f4 units)
    float* sx  = smem + FIN * FH;    // 128 rows x 128 k, linear
    int t = threadIdx.x;

    #pragma unroll
    for (int i = t; i < FIN * FH; i += G1_THREADS) {
        int k = i >> 6, col = i & 63;
        int unit = col * 32 + ((k >> 2) ^ (col & 31));
        sWt[unit * 4 + (k & 3)] = W1[i];
    }

    int rowBase = blockIdx.x * G1_ROWS;
    #pragma unroll
    for (int i = t; i < G1_ROWS * FIN / 4; i += G1_THREADS) {
        int r = i / (FIN / 4), c = i % (FIN / 4);
        int row = rowBase + r;
        float4 val = (row < n) ? ((const float4*)(x + (size_t)row * FIN))[c]
                               : make_float4(0.f, 0.f, 0.f, 0.f);
        ((float4*)(sx + r * FIN))[c] = val;
    }
    __syncthreads();

    int cp = t & 31;
    int rg = t >> 5;

    uint32_t wbase = (uint32_t)__cvta_generic_to_shared(sWt);
    uint32_t xbase = (uint32_t)__cvta_generic_to_shared(sx + (rg * 8) * FIN);

    uint64_t accA[8], accB[8];
    #pragma unroll
    for (int i = 0; i < 8; i++) { accA[i] = 0ull; accB[i] = 0ull; }

    #pragma unroll
    for (int k4 = 0; k4 < FIN / 4; k4++) {
        int sw = k4 ^ cp;
        uint64_t wA01, wA23, wB01, wB23;
        uint32_t waddrA = wbase + (uint32_t)((cp * 32 + sw) * 16);
        uint32_t waddrB = waddrA + (uint32_t)(32 * 32 * 16);
        asm volatile("ld.shared.v2.b64 {%0, %1}, [%2];"
                     : "=l"(wA01), "=l"(wA23) : "r"(waddrA));
        asm volatile("ld.shared.v2.b64 {%0, %1}, [%2];"
                     : "=l"(wB01), "=l"(wB23) : "r"(waddrB));
        #pragma unroll
        for (int i = 0; i < 8; i++) {
            uint64_t x01, x23;
            uint32_t xaddr = xbase + (uint32_t)(i * FIN * 4 + k4 * 16);
            asm volatile("ld.shared.v2.b64 {%0, %1}, [%2];"
                         : "=l"(x01), "=l"(x23) : "r"(xaddr));
            asm volatile("fma.rn.f32x2 %0, %1, %2, %0;"
                         : "+l"(accA[i]) : "l"(x01), "l"(wA01));
            asm volatile("fma.rn.f32x2 %0, %1, %2, %0;"
                         : "+l"(accA[i]) : "l"(x23), "l"(wA23));
            asm volatile("fma.rn.f32x2 %0, %1, %2, %0;"
                         : "+l"(accB[i]) : "l"(x01), "l"(wB01));
            asm volatile("fma.rn.f32x2 %0, %1, %2, %0;"
                         : "+l"(accB[i]) : "l"(x23), "l"(wB23));
        }
    }

    __half* h1 = (__half*)g_h1h;
    #pragma unroll
    for (int i = 0; i < 8; i++) {
        int row = rowBase + rg * 8 + i;
        if (row < n) {
            float a = __uint_as_float((uint32_t)(accA[i] & 0xffffffffull))
                    + __uint_as_float((uint32_t)(accA[i] >> 32));
            float b = __uint_as_float((uint32_t)(accB[i] & 0xffffffffull))
                    + __uint_as_float((uint32_t)(accB[i] >> 32));
            h1[(size_t)row * FH + cp]      = __float2half(a);
            h1[(size_t)row * FH + cp + 32] = __float2half(b);
        }
    }
}

// ---------------------------------------------------------------------------
// scan1: decode packed (count, deg), per-block inclusive scan, fused dinv
// ---------------------------------------------------------------------------
__global__ void scan1_kernel(int n) {
    __shared__ int s[SCAN_B];
    int t = threadIdx.x;
    int gid = blockIdx.x * SCAN_B + t;
    int v = 0;
    if (gid < n) {
        unsigned long long p = g_packed[gid];
        v = (int)(p >> 40);
        float deg = (float)(p & 0xFFFFFFFFFFull) * (1.0f / 16777216.0f);
        g_dinv[gid] = rsqrtf(deg);
        g_cnt[gid] = v;
    }
    s[t] = v;
    __syncthreads();
    #pragma unroll
    for (int off = 1; off < SCAN_B; off <<= 1) {
        int u = (t >= off) ? s[t - off] : 0;
        __syncthreads();
        s[t] += u;
        __syncthreads();
    }
    if (gid < n) g_rowstart[gid] = s[t] - v;
    if (t == SCAN_B - 1) g_blocksum[blockIdx.x] = s[t];
}

__global__ void scan2_kernel(int nb) {
    __shared__ int s[MAXBLK];
    int t = threadIdx.x;
    int v = (t < nb) ? g_blocksum[t] : 0;
    s[t] = v;
    __syncthreads();
    #pragma unroll
    for (int off = 1; off < MAXBLK; off <<= 1) {
        int u = (t >= off) ? s[t - off] : 0;
        __syncthreads();
        s[t] += u;
        __syncthreads();
    }
    if (t < nb) g_blocksum[t] = s[t] - v;
}

__global__ void scan3_kernel(int n) {
    int gid = blockIdx.x * blockDim.x + threadIdx.x;
    if (gid >= n) return;
    int r = g_rowstart[gid] + g_blocksum[gid >> 10];
    g_rowstart[gid] = r;
    g_cursor[gid] = r;
}

__global__ void build_kernel(const void* __restrict__ ei,
                             const float* __restrict__ ew, int E) {
    int e = blockIdx.x * blockDim.x + threadIdx.x;
    if (e >= E) return;
    int s = edge_src(ei, E, e);
    int d = edge_dst(ei, E, e);
    int pos = atomicAdd(&g_cursor[d], 1);
    float nm = g_dinv[s] * ew[e] * g_dinv[d];
    g_edge[pos] = make_int2(s, __float_as_int(nm));
}

// ---------------------------------------------------------------------------
// agg1: one warp per dst node; lanes own 2 features (half2); fp32 accumulate
// ---------------------------------------------------------------------------
__global__ void agg1_kernel(const float* __restrict__ b1, int n) {
    int warp = (blockIdx.x * blockDim.x + threadIdx.x) >> 5;
    if (warp >= n) return;
    int lane = threadIdx.x & 31;
    const __half2* h1 = g_h1h;    // [n][32] half2
    int start = g_rowstart[warp];
    int end = start + g_cnt[warp];
    float2 acc = make_float2(0.f, 0.f);

    int j = start;
    for (; j + 8 <= end; j += 8) {
        int2 e0 = g_edge[j],   e1 = g_edge[j+1], e2 = g_edge[j+2], e3 = g_edge[j+3];
        int2 e4 = g_edge[j+4], e5 = g_edge[j+5], e6 = g_edge[j+6], e7 = g_edge[j+7];
        float2 v0 = __half22float2(h1[(size_t)e0.x * 32 + lane]);
        float2 v1 = __half22float2(h1[(size_t)e1.x * 32 + lane]);
        float2 v2 = __half22float2(h1[(size_t)e2.x * 32 + lane]);
        float2 v3 = __half22float2(h1[(size_t)e3.x * 32 + lane]);
        float2 v4 = __half22float2(h1[(size_t)e4.x * 32 + lane]);
        float2 v5 = __half22float2(h1[(size_t)e5.x * 32 + lane]);
        float2 v6 = __half22float2(h1[(size_t)e6.x * 32 + lane]);
        float2 v7 = __half22float2(h1[(size_t)e7.x * 32 + lane]);
        float n0 = __int_as_float(e0.y), n1 = __int_as_float(e1.y);
        float n2 = __int_as_float(e2.y), n3 = __int_as_float(e3.y);
        float n4 = __int_as_float(e4.y), n5 = __int_as_float(e5.y);
        float n6 = __int_as_float(e6.y), n7 = __int_as_float(e7.y);
        acc.x += n0 * v0.x + n1 * v1.x + n2 * v2.x + n3 * v3.x
               + n4 * v4.x + n5 * v5.x + n6 * v6.x + n7 * v7.x;
        acc.y += n0 * v0.y + n1 * v1.y + n2 * v2.y + n3 * v3.y
               + n4 * v4.y + n5 * v5.y + n6 * v6.y + n7 * v7.y;
    }
    for (; j < end; j++) {
        int2 e = g_edge[j];
        float nm = __int_as_float(e.y);
        float2 v = __half22float2(h1[(size_t)e.x * 32 + lane]);
        acc.x += nm * v.x;
        acc.y += nm * v.y;
    }
    float dv = g_dinv[warp];
    float self = dv * dv;
    float2 hs = __half22float2(h1[(size_t)warp * 32 + lane]);
    acc.x += self * hs.x;
    acc.y += self * hs.y;
    acc.x = fmaxf(acc.x + b1[lane * 2 + 0], 0.f);
    acc.y = fmaxf(acc.y + b1[lane * 2 + 1], 0.f);
    ((float2*)g_z)[(size_t)warp * 32 + lane] = acc;
}

// ---------------------------------------------------------------------------
__global__ void gemm2_kernel(const float* __restrict__ W2, int n) {
    __shared__ float sW[FH * FO];
    for (int i = threadIdx.x; i < FH * FO; i += blockDim.x) sW[i] = W2[i];
    __syncthreads();

    int nn = blockIdx.x * blockDim.x + threadIdx.x;
    if (nn >= n) return;
    const float4* z4 = &g_z[(size_t)nn * (FH / 4)];
    float acc[FO];
    #pragma unroll
    for (int j = 0; j < FO; j++) acc[j] = 0.f;
    #pragma unroll
    for (int k4 = 0; k4 < FH / 4; k4++) {
        float4 zv = z4[k4];
        #pragma unroll
        for (int j = 0; j < FO; j++) {
            acc[j] += zv.x * sW[(k4 * 4 + 0) * FO + j];
            acc[j] += zv.y * sW[(k4 * 4 + 1) * FO + j];
            acc[j] += zv.z * sW[(k4 * 4 + 2) * FO + j];
            acc[j] += zv.w * sW[(k4 * 4 + 3) * FO + j];
        }
    }
    float4* o4 = &g_h2[(size_t)nn * (FO / 4)];
    o4[0] = make_float4(acc[0], acc[1], acc[2], acc[3]);
    o4[1] = make_float4(acc[4], acc[5], acc[6], acc[7]);
    o4[2] = make_float4(acc[8], acc[9], acc[10], acc[11]);
    o4[3] = make_float4(acc[12], acc[13], acc[14], acc[15]);
}

// ---------------------------------------------------------------------------
__global__ void agg2_kernel(const float* __restrict__ b2,
                            float* __restrict__ out, int n) {
    int gid = blockIdx.x * blockDim.x + threadIdx.x;
    int node = gid >> 4;
    bool live = node < n;
    if (!live) node = 0;
    int f = gid & 15;
    const float* h2 = (const float*)g_h2;
    int start = g_rowstart[node];
    int end = start + g_cnt[node];
    float acc = 0.f;

    int j = start;
    for (; j + 4 <= end; j += 4) {
        int2 e0 = g_edge[j],   e1 = g_edge[j+1];
        int2 e2 = g_edge[j+2], e3 = g_edge[j+3];
        acc += __int_as_float(e0.y) * h2[(size_t)e0.x * FO + f]
             + __int_as_float(e1.y) * h2[(size_t)e1.x * FO + f]
             + __int_as_float(e2.y) * h2[(size_t)e2.x * FO + f]
             + __int_as_float(e3.y) * h2[(size_t)e3.x * FO + f];
    }
    for (; j < end; j++) {
        int2 e = g_edge[j];
        acc += __int_as_float(e.y) * h2[(size_t)e.x * FO + f];
    }
    float dv = g_dinv[node];
    acc += dv * dv * h2[(size_t)node * FO + f] + b2[f];

    float m = acc;
    #pragma unroll
    for (int off = 8; off > 0; off >>= 1)
        m = fmaxf(m, __shfl_xor_sync(0xffffffffu, m, off));
    float e = expf(acc - m);
    float ssum = e;
    #pragma unroll
    for (int off = 8; off > 0; off >>= 1)
        ssum += __shfl_xor_sync(0xffffffffu, ssum, off);
    if (live) out[(size_t)node * FO + f] = acc - m - logf(ssum);
}

// ---------------------------------------------------------------------------
extern "C" void kernel_launch(void* const* d_in, const int* in_sizes, int n_in,
                              void* d_out, int out_size) {
    const float* x  = (const float*)d_in[0];
    const void*  ei = d_in[1];
    const float* ew = (const float*)d_in[2];
    const float* W1 = (const float*)d_in[3];
    const float* b1 = (const float*)d_in[4];
    const float* W2 = (const float*)d_in[5];
    const float* b2 = (const float*)d_in[6];
    float*       out = (float*)d_out;

    int n = in_sizes[0] / FIN;
    int E = in_sizes[2];

    static cudaStream_t s1 = nullptr;
    static cudaEvent_t evFork = nullptr, evJoin = nullptr;
    static bool inited = false;
    if (!inited) {
        cudaStreamCreateWithFlags(&s1, cudaStreamNonBlocking);
        cudaEventCreateWithFlags(&evFork, cudaEventDisableTiming);
        cudaEventCreateWithFlags(&evJoin, cudaEventDisableTiming);
        cudaFuncSetAttribute(gemm1_kernel,
                             cudaFuncAttributeMaxDynamicSharedMemorySize, G1_SMEM);
        inited = true;
    }

    // fork FIRST: gemm1 overlaps the entire CSR chain
    cudaEventRecord(evFork, 0);
    cudaStreamWaitEvent(s1, evFork, 0);
    gemm1_kernel<<<(n + G1_ROWS - 1) / G1_ROWS, G1_THREADS, G1_SMEM, s1>>>(x, W1, n);
    cudaEventRecord(evJoin, s1);

    // main stream: CSR chain  (4th kernel launch overall = cnt -> ncu)
    probe_kernel<<<1, 1>>>(ei, E, n);
    init_kernel<<<(n + 255) / 256, 256>>>(n);
    cnt_kernel<<<(E + 255) / 256, 256>>>(ei, ew, E);

    int nb = (n + SCAN_B - 1) / SCAN_B;
    scan1_kernel<<<nb, SCAN_B>>>(n);
    scan2_kernel<<<1, MAXBLK>>>(nb);
    scan3_kernel<<<(n + 255) / 256, 256>>>(n);

    build_kernel<<<(E + 255) / 256, 256>>>(ei, ew, E);

    // join: agg1 needs h1 (side stream) and CSR (main stream)
    cudaStreamWaitEvent(0, evJoin, 0);

    long long tw = (long long)n * 32;
    agg1_kernel<<<(int)((tw + 255) / 256), 256>>>(b1, n);

    gemm2_kernel<<<(n + 255) / 256, 256>>>(W2, n);

    long long t2 = (long long)n * 16;
    agg2_kernel<<<(int)((t2 + 255) / 256), 256>>>(b2, out, n);
}

// round 14
// speedup vs baseline: 1.4684x; 1.0969x over previous
#include <cuda_runtime.h>
#include <cuda_fp16.h>
#include <cstdint>

#define MAXN 100000
#define MAXE 1600000
#define FIN 128
#define FH 64
#define FO 16
#define SCAN_B 1024
#define MAXBLK 128
#define GM_ROWS 128
#define GM_THREADS 256
#define XS_STRIDE 136   // halfs per row (128 + 8 pad) -> conflict-free frags
#define WS_STRIDE 136
#define GM_SMEM ((GM_ROWS * XS_STRIDE + FH * WS_STRIDE) * 2)  // ~52KB

// Scratch (device globals: allocation-free)
__device__ int                g_is64;
__device__ unsigned long long g_packed[MAXN];   // count<<40 | deg_fixed(2^-24)
__device__ float              g_dinv[MAXN];
__device__ int                g_cnt[MAXN];
__device__ int                g_rowstart[MAXN];
__device__ int                g_cursor[MAXN];
__device__ int                g_blocksum[MAXBLK];
__device__ int2               g_edge[MAXE];     // {src, norm bits}
__device__ __half2            g_h1h[(size_t)MAXN * (FH / 2)];  // fp16 h1 [n][64]
__device__ float4             g_z [(size_t)MAXN * (FH / 4)];
__device__ __half2            g_h2h[(size_t)MAXN * (FO / 2)];  // fp16 h2 [n][16]

__device__ __forceinline__ int edge_src(const void* ei, int E, int e) {
    return g_is64 ? (int)((const long long*)ei)[e] : ((const int*)ei)[e];
}
__device__ __forceinline__ int edge_dst(const void* ei, int E, int e) {
    return g_is64 ? (int)((const long long*)ei)[(size_t)E + e]
                  : ((const int*)ei)[(size_t)E + e];
}

// ---------------------------------------------------------------------------
__global__ void probe_kernel(const void* ei, int E, int n) {
    if (threadIdx.x != 0 || blockIdx.x != 0) return;
    const long long* p = (const long long*)ei;
    int ok64 = 1;
    int m = E < 64 ? E : 64;
    for (int i = 0; i < m; i++) {
        long long v = p[i];
        long long w = p[(size_t)E + i];
        if (v < 0 || v >= n || w < 0 || w >= n) { ok64 = 0; break; }
    }
    g_is64 = ok64;
}

__global__ void init_kernel(int n) {
    int i = blockIdx.x * blockDim.x + threadIdx.x;
    if (i < n) g_packed[i] = (unsigned long long)1 << 24;  // deg = 1.0 fixed
}

// ONE 64-bit atomic per edge
__global__ void cnt_kernel(const void* __restrict__ ei,
                           const float* __restrict__ ew, int E) {
    int e = blockIdx.x * blockDim.x + threadIdx.x;
    if (e >= E) return;
    int d = edge_dst(ei, E, e);
    unsigned long long add =
        ((unsigned long long)1 << 40) +
        (unsigned long long)__float2uint_rn(ew[e] * 16777216.0f);
    atomicAdd(&g_packed[d], add);
}

// ---------------------------------------------------------------------------
// h1 = x @ W1 on tensor cores: mma.sync m16n8k16 f16->f32.
// Block: 256 thr = 8 warps (4 M x 2 N), tile 128x64, K=128 (8 k-steps).
// x, W1^T staged in smem as fp16, padded stride 136 (conflict-free frag LDS).
// ---------------------------------------------------------------------------
__global__ void __launch_bounds__(GM_THREADS)
gemm1_kernel(const float* __restrict__ x,
             const float* __restrict__ W1, int n) {
    extern __shared__ __half sm[];
    __half* xs = sm;                          // [128][136]
    __half* ws = sm + GM_ROWS * XS_STRIDE;    // [64][136]  ws[col][k] = W1[k][col]
    int t = threadIdx.x;

    // W1 [k][col] -> ws[col][k] (fp16)
    for (int i = t; i < FIN * FH / 4; i += GM_THREADS) {
        int k = i / (FH / 4);
        int c = (i % (FH / 4)) * 4;
        float4 w = ((const float4*)W1)[i];
        ws[(c + 0) * WS_STRIDE + k] = __float2half(w.x);
        ws[(c + 1) * WS_STRIDE + k] = __float2half(w.y);
        ws[(c + 2) * WS_STRIDE + k] = __float2half(w.z);
        ws[(c + 3) * WS_STRIDE + k] = __float2half(w.w);
    }

    int rowBase = blockIdx.x * GM_ROWS;
    for (int i = t; i < GM_ROWS * FIN / 4; i += GM_THREADS) {
        int r = i / (FIN / 4), c4 = i % (FIN / 4);
        int row = rowBase + r;
        float4 v = (row < n) ? ((const float4*)(x + (size_t)row * FIN))[c4]
                             : make_float4(0.f, 0.f, 0.f, 0.f);
        __half2* dst = (__half2*)(xs + r * XS_STRIDE + c4 * 4);
        dst[0] = __floats2half2_rn(v.x, v.y);
        dst[1] = __floats2half2_rn(v.z, v.w);
    }
    __syncthreads();

    int warp = t >> 5, lane = t & 31;
    int mw = (warp >> 1) * 32;     // 0,32,64,96
    int nw = (warp & 1) * 32;      // 0,32
    int gr = lane >> 2;            // 0..7
    int tg = lane & 3;             // 0..3

    float c[2][4][4];
    #pragma unroll
    for (int i = 0; i < 2; i++)
        #pragma unroll
        for (int j = 0; j < 4; j++)
            #pragma unroll
            for (int q = 0; q < 4; q++) c[i][j][q] = 0.f;

    #pragma unroll
    for (int ks = 0; ks < FIN / 16; ks++) {
        int k0 = ks * 16;
        uint32_t a[2][4];
        #pragma unroll
        for (int mi = 0; mi < 2; mi++) {
            const __half* base = xs + (mw + mi * 16 + gr) * XS_STRIDE + k0 + tg * 2;
            a[mi][0] = *(const uint32_t*)(base);
            a[mi][1] = *(const uint32_t*)(base + 8 * XS_STRIDE);
            a[mi][2] = *(const uint32_t*)(base + 8);
            a[mi][3] = *(const uint32_t*)(base + 8 * XS_STRIDE + 8);
        }
        uint32_t b[4][2];
        #pragma unroll
        for (int ni = 0; ni < 4; ni++) {
            const __half* base = ws + (nw + ni * 8 + gr) * WS_STRIDE + k0 + tg * 2;
            b[ni][0] = *(const uint32_t*)(base);
            b[ni][1] = *(const uint32_t*)(base + 8);
        }
        #pragma unroll
        for (int mi = 0; mi < 2; mi++)
            #pragma unroll
            for (int ni = 0; ni < 4; ni++)
                asm volatile(
                    "mma.sync.aligned.m16n8k16.row.col.f32.f16.f16.f32 "
                    "{%0,%1,%2,%3}, {%4,%5,%6,%7}, {%8,%9}, {%0,%1,%2,%3};"
                    : "+f"(c[mi][ni][0]), "+f"(c[mi][ni][1]),
                      "+f"(c[mi][ni][2]), "+f"(c[mi][ni][3])
                    : "r"(a[mi][0]), "r"(a[mi][1]), "r"(a[mi][2]), "r"(a[mi][3]),
                      "r"(b[ni][0]), "r"(b[ni][1]));
    }

    // epilogue: h1 fp16. c0,c1 -> row gr, cols tg*2,+1; c2,c3 -> row gr+8.
    #pragma unroll
    for (int mi = 0; mi < 2; mi++) {
        #pragma unroll
        for (int ni = 0; ni < 4; ni++) {
            int col2 = (nw + ni * 8 + tg * 2) >> 1;   // half2 index
            int row0 = rowBase + mw + mi * 16 + gr;
            int row1 = row0 + 8;
            if (row0 < n)
                g_h1h[(size_t)row0 * 32 + col2] =
                    __floats2half2_rn(c[mi][ni][0], c[mi][ni][1]);
            if (row1 < n)
                g_h1h[(size_t)row1 * 32 + col2] =
                    __floats2half2_rn(c[mi][ni][2], c[mi][ni][3]);
        }
    }
}

// ---------------------------------------------------------------------------
__global__ void scan1_kernel(int n) {
    __shared__ int s[SCAN_B];
    int t = threadIdx.x;
    int gid = blockIdx.x * SCAN_B + t;
    int v = 0;
    if (gid < n) {
        unsigned long long p = g_packed[gid];
        v = (int)(p >> 40);
        float deg = (float)(p & 0xFFFFFFFFFFull) * (1.0f / 16777216.0f);
        g_dinv[gid] = rsqrtf(deg);
        g_cnt[gid] = v;
    }
    s[t] = v;
    __syncthreads();
    #pragma unroll
    for (int off = 1; off < SCAN_B; off <<= 1) {
        int u = (t >= off) ? s[t - off] : 0;
        __syncthreads();
        s[t] += u;
        __syncthreads();
    }
    if (gid < n) g_rowstart[gid] = s[t] - v;
    if (t == SCAN_B - 1) g_blocksum[blockIdx.x] = s[t];
}

__global__ void scan2_kernel(int nb) {
    __shared__ int s[MAXBLK];
    int t = threadIdx.x;
    int v = (t < nb) ? g_blocksum[t] : 0;
    s[t] = v;
    __syncthreads();
    #pragma unroll
    for (int off = 1; off < MAXBLK; off <<= 1) {
        int u = (t >= off) ? s[t - off] : 0;
        __syncthreads();
        s[t] += u;
        __syncthreads();
    }
    if (t < nb) g_blocksum[t] = s[t] - v;
}

__global__ void scan3_kernel(int n) {
    int gid = blockIdx.x * blockDim.x + threadIdx.x;
    if (gid >= n) return;
    int r = g_rowstart[gid] + g_blocksum[gid >> 10];
    g_rowstart[gid] = r;
    g_cursor[gid] = r;
}

__global__ void build_kernel(const void* __restrict__ ei,
                             const float* __restrict__ ew, int E) {
    int e = blockIdx.x * blockDim.x + threadIdx.x;
    if (e >= E) return;
    int s = edge_src(ei, E, e);
    int d = edge_dst(ei, E, e);
    int pos = atomicAdd(&g_cursor[d], 1);
    float nm = g_dinv[s] * ew[e] * g_dinv[d];
    g_edge[pos] = make_int2(s, __float_as_int(nm));
}

// ---------------------------------------------------------------------------
// agg1: one warp per dst node; lanes own 2 features (half2); fp32 accumulate
// ---------------------------------------------------------------------------
__global__ void agg1_kernel(const float* __restrict__ b1, int n) {
    int warp = (blockIdx.x * blockDim.x + threadIdx.x) >> 5;
    if (warp >= n) return;
    int lane = threadIdx.x & 31;
    const __half2* h1 = g_h1h;
    int start = g_rowstart[warp];
    int end = start + g_cnt[warp];
    float2 acc = make_float2(0.f, 0.f);

    int j = start;
    for (; j + 8 <= end; j += 8) {
        int2 e0 = g_edge[j],   e1 = g_edge[j+1], e2 = g_edge[j+2], e3 = g_edge[j+3];
        int2 e4 = g_edge[j+4], e5 = g_edge[j+5], e6 = g_edge[j+6], e7 = g_edge[j+7];
        float2 v0 = __half22float2(h1[(size_t)e0.x * 32 + lane]);
        float2 v1 = __half22float2(h1[(size_t)e1.x * 32 + lane]);
        float2 v2 = __half22float2(h1[(size_t)e2.x * 32 + lane]);
        float2 v3 = __half22float2(h1[(size_t)e3.x * 32 + lane]);
        float2 v4 = __half22float2(h1[(size_t)e4.x * 32 + lane]);
        float2 v5 = __half22float2(h1[(size_t)e5.x * 32 + lane]);
        float2 v6 = __half22float2(h1[(size_t)e6.x * 32 + lane]);
        float2 v7 = __half22float2(h1[(size_t)e7.x * 32 + lane]);
        float n0 = __int_as_float(e0.y), n1 = __int_as_float(e1.y);
        float n2 = __int_as_float(e2.y), n3 = __int_as_float(e3.y);
        float n4 = __int_as_float(e4.y), n5 = __int_as_float(e5.y);
        float n6 = __int_as_float(e6.y), n7 = __int_as_float(e7.y);
        acc.x += n0 * v0.x + n1 * v1.x + n2 * v2.x + n3 * v3.x
               + n4 * v4.x + n5 * v5.x + n6 * v6.x + n7 * v7.x;
        acc.y += n0 * v0.y + n1 * v1.y + n2 * v2.y + n3 * v3.y
               + n4 * v4.y + n5 * v5.y + n6 * v6.y + n7 * v7.y;
    }
    for (; j < end; j++) {
        int2 e = g_edge[j];
        float nm = __int_as_float(e.y);
        float2 v = __half22float2(h1[(size_t)e.x * 32 + lane]);
        acc.x += nm * v.x;
        acc.y += nm * v.y;
    }
    float dv = g_dinv[warp];
    float self = dv * dv;
    float2 hs = __half22float2(h1[(size_t)warp * 32 + lane]);
    acc.x += self * hs.x;
    acc.y += self * hs.y;
    acc.x = fmaxf(acc.x + b1[lane * 2 + 0], 0.f);
    acc.y = fmaxf(acc.y + b1[lane * 2 + 1], 0.f);
    ((float2*)g_z)[(size_t)warp * 32 + lane] = acc;
}

// ---------------------------------------------------------------------------
__global__ void gemm2_kernel(const float* __restrict__ W2, int n) {
    __shared__ float sW[FH * FO];
    for (int i = threadIdx.x; i < FH * FO; i += blockDim.x) sW[i] = W2[i];
    __syncthreads();

    int nn = blockIdx.x * blockDim.x + threadIdx.x;
    if (nn >= n) return;
    const float4* z4 = &g_z[(size_t)nn * (FH / 4)];
    float acc[FO];
    #pragma unroll
    for (int j = 0; j < FO; j++) acc[j] = 0.f;
    #pragma unroll
    for (int k4 = 0; k4 < FH / 4; k4++) {
        float4 zv = z4[k4];
        #pragma unroll
        for (int j = 0; j < FO; j++) {
            acc[j] += zv.x * sW[(k4 * 4 + 0) * FO + j];
            acc[j] += zv.y * sW[(k4 * 4 + 1) * FO + j];
            acc[j] += zv.z * sW[(k4 * 4 + 2) * FO + j];
            acc[j] += zv.w * sW[(k4 * 4 + 3) * FO + j];
        }
    }
    __half2* o2 = &g_h2h[(size_t)nn * (FO / 2)];
    #pragma unroll
    for (int q = 0; q < FO / 2; q++)
        o2[q] = __floats2half2_rn(acc[q * 2], acc[q * 2 + 1]);
}

// ---------------------------------------------------------------------------
__global__ void agg2_kernel(const float* __restrict__ b2,
                            float* __restrict__ out, int n) {
    int gid = blockIdx.x * blockDim.x + threadIdx.x;
    int node = gid >> 4;
    bool live = node < n;
    if (!live) node = 0;
    int f = gid & 15;
    const __half* h2 = (const __half*)g_h2h;
    int start = g_rowstart[node];
    int end = start + g_cnt[node];
    float acc = 0.f;

    int j = start;
    for (; j + 4 <= end; j += 4) {
        int2 e0 = g_edge[j],   e1 = g_edge[j+1];
        int2 e2 = g_edge[j+2], e3 = g_edge[j+3];
        acc += __int_as_float(e0.y) * __half2float(h2[(size_t)e0.x * FO + f])
             + __int_as_float(e1.y) * __half2float(h2[(size_t)e1.x * FO + f])
             + __int_as_float(e2.y) * __half2float(h2[(size_t)e2.x * FO + f])
             + __int_as_float(e3.y) * __half2float(h2[(size_t)e3.x * FO + f]);
    }
    for (; j < end; j++) {
        int2 e = g_edge[j];
        acc += __int_as_float(e.y) * __half2float(h2[(size_t)e.x * FO + f]);
    }
    float dv = g_dinv[node];
    acc += dv * dv * __half2float(h2[(size_t)node * FO + f]) + b2[f];

    float m = acc;
    #pragma unroll
    for (int off = 8; off > 0; off >>= 1)
        m = fmaxf(m, __shfl_xor_sync(0xffffffffu, m, off));
    float e = expf(acc - m);
    float ssum = e;
    #pragma unroll
    for (int off = 8; off > 0; off >>= 1)
        ssum += __shfl_xor_sync(0xffffffffu, ssum, off);
    if (live) out[(size_t)node * FO + f] = acc - m - logf(ssum);
}

// ---------------------------------------------------------------------------
extern "C" void kernel_launch(void* const* d_in, const int* in_sizes, int n_in,
                              void* d_out, int out_size) {
    const float* x  = (const float*)d_in[0];
    const void*  ei = d_in[1];
    const float* ew = (const float*)d_in[2];
    const float* W1 = (const float*)d_in[3];
    const float* b1 = (const float*)d_in[4];
    const float* W2 = (const float*)d_in[5];
    const float* b2 = (const float*)d_in[6];
    float*       out = (float*)d_out;

    int n = in_sizes[0] / FIN;
    int E = in_sizes[2];

    static cudaStream_t s1 = nullptr;
    static cudaEvent_t evFork = nullptr, evJoin = nullptr;
    static bool inited = false;
    if (!inited) {
        cudaStreamCreateWithFlags(&s1, cudaStreamNonBlocking);
        cudaEventCreateWithFlags(&evFork, cudaEventDisableTiming);
        cudaEventCreateWithFlags(&evJoin, cudaEventDisableTiming);
        cudaFuncSetAttribute(gemm1_kernel,
                             cudaFuncAttributeMaxDynamicSharedMemorySize, GM_SMEM);
        inited = true;
    }

    // fork FIRST: gemm1 overlaps the entire CSR chain
    cudaEventRecord(evFork, 0);
    cudaStreamWaitEvent(s1, evFork, 0);
    gemm1_kernel<<<(n + GM_ROWS - 1) / GM_ROWS, GM_THREADS, GM_SMEM, s1>>>(x, W1, n);
    cudaEventRecord(evJoin, s1);

    // main stream: CSR chain
    probe_kernel<<<1, 1>>>(ei, E, n);
    init_kernel<<<(n + 255) / 256, 256>>>(n);
    cnt_kernel<<<(E + 255) / 256, 256>>>(ei, ew, E);

    int nb = (n + SCAN_B - 1) / SCAN_B;
    scan1_kernel<<<nb, SCAN_B>>>(n);
    scan2_kernel<<<1, MAXBLK>>>(nb);
    scan3_kernel<<<(n + 255) / 256, 256>>>(n);

    build_kernel<<<(E + 255) / 256, 256>>>(ei, ew, E);

    // join: agg1 needs h1 (side stream) and CSR (main stream)
    cudaStreamWaitEvent(0, evJoin, 0);

    long long tw = (long long)n * 32;
    agg1_kernel<<<(int)((tw + 255) / 256), 256>>>(b1, n);

    gemm2_kernel<<<(n + 255) / 256, 256>>>(W2, n);

    long long t2 = (long long)n * 16;
    agg2_kernel<<<(int)((t2 + 255) / 256), 256>>>(b2, out, n);
}